// round 1
// baseline (speedup 1.0000x reference)
#include <cuda_runtime.h>
#include <math.h>

// ---------------- problem constants ----------------
#define SEQ      4096
#define HIDDEN   1152
#define HEADS    16
#define HD       72
#define INTER    4304
#define DEPTH    6
#define MERGED   4608
#define OUTH     2048
#define PATCHD   1536
#define IMG_TOK  1024
#define NBH      64     // 4 images * 16 heads
#define SCALE_Q  0.11785113019775793f   // 72^-0.5

// ---------------- device scratch (static, no allocations) ----------------
__device__ float g_x   [SEQ*HIDDEN];
__device__ float g_xn  [SEQ*HIDDEN];
__device__ float g_qkv [SEQ*3*HIDDEN];
__device__ float g_q2  [NBH*IMG_TOK*HD];
__device__ float g_k2  [NBH*IMG_TOK*HD];
__device__ float g_v2  [NBH*IMG_TOK*HD];
__device__ float g_sc  [67108864];           // 64*1024*1024 scores
__device__ float g_o2  [NBH*IMG_TOK*HD];
__device__ float g_attn[SEQ*HIDDEN];
__device__ float g_h   [SEQ*INTER];
__device__ float g_mh  [SEQ*HIDDEN];         // also viewed as [1024][4608]
__device__ float g_mf  [1024*MERGED];
__device__ float g_cos [IMG_TOK*HD];
__device__ float g_sin [IMG_TOK*HD];

// ---------------- helpers ----------------
__device__ __forceinline__ float gelu_f(float x){
    float x3 = x*x*x;
    return 0.5f*x*(1.0f + tanhf(0.7978845608028654f*(x + 0.044715f*x3)));
}

__device__ __forceinline__ float blockReduceSum(float v, float* sh){
    int tid = threadIdx.x;
    __syncthreads();
    #pragma unroll
    for(int o=16;o>0;o>>=1) v += __shfl_xor_sync(0xffffffffu, v, o);
    if((tid&31)==0) sh[tid>>5] = v;
    __syncthreads();
    if(tid < 32){
        float r = (tid < (int)(blockDim.x>>5)) ? sh[tid] : 0.f;
        #pragma unroll
        for(int o=16;o>0;o>>=1) r += __shfl_xor_sync(0xffffffffu, r, o);
        if(tid==0) sh[0] = r;
    }
    __syncthreads();
    return sh[0];
}

__device__ __forceinline__ float blockReduceMax(float v, float* sh){
    int tid = threadIdx.x;
    __syncthreads();
    #pragma unroll
    for(int o=16;o>0;o>>=1) v = fmaxf(v, __shfl_xor_sync(0xffffffffu, v, o));
    if((tid&31)==0) sh[tid>>5] = v;
    __syncthreads();
    if(tid < 32){
        float r = (tid < (int)(blockDim.x>>5)) ? sh[tid] : -3.4e38f;
        #pragma unroll
        for(int o=16;o>0;o>>=1) r = fmaxf(r, __shfl_xor_sync(0xffffffffu, r, o));
        if(tid==0) sh[0] = r;
    }
    __syncthreads();
    return sh[0];
}

// ---------------- GEMM: C = A @ op(B) + bias [+gelu] [+res] ----------------
// BT=1: B is [N,K] row-major (x @ W.T, weight layout).  BT=0: B is [K,N] row-major.
// A is [M,K] row-major. M % 128 == 0 and K % 8 == 0 are required (true everywhere).
// N may be arbitrary (guarded).
template<int BT>
__global__ void gemm128(const float* __restrict__ A, const float* __restrict__ B,
                        float* __restrict__ C, const float* __restrict__ bias,
                        const float* __restrict__ res,
                        int M, int N, int K,
                        long sA, long sB, long sC, int dogelu)
{
    __shared__ float As[8][128];
    __shared__ float Bs[8][128];
    const int tid = threadIdx.x;
    const int bn = blockIdx.x, bm = blockIdx.y, bz = blockIdx.z;
    const float* Ab = A + (long)bz*sA;
    const float* Bb = B + (long)bz*sB;
    float*       Cb = C + (long)bz*sC;
    const float* Rb = res ? (res + (long)bz*sC) : (const float*)0;

    const int alr = tid >> 1;            // 0..127
    const int alk = (tid & 1) * 4;       // 0 or 4
    const long abase = (long)(bm*128 + alr)*K + alk;

    const int bkr  = tid >> 5;           // 0..7   (NN path)
    const int bcl  = (tid & 31) * 4;     // 0..124
    const int bcol = bn*128 + bcl;

    const int tx = tid & 15, ty = tid >> 4;

    float acc[8][8];
    #pragma unroll
    for(int i=0;i<8;i++)
        #pragma unroll
        for(int j=0;j<8;j++) acc[i][j]=0.f;

    for(int k0=0;k0<K;k0+=8){
        float4 av = *(const float4*)(Ab + abase + k0);
        float4 bv;
        if(BT){
            int brow = bn*128 + alr;
            if(brow < N) bv = *(const float4*)(Bb + (long)brow*K + k0 + alk);
            else         bv = make_float4(0.f,0.f,0.f,0.f);
        } else {
            const float* bp = Bb + (long)(k0+bkr)*N + bcol;
            if(bcol+3 < N) bv = *(const float4*)bp;
            else {
                bv.x = (bcol+0<N)?bp[0]:0.f;
                bv.y = (bcol+1<N)?bp[1]:0.f;
                bv.z = (bcol+2<N)?bp[2]:0.f;
                bv.w = (bcol+3<N)?bp[3]:0.f;
            }
        }
        __syncthreads();
        As[alk+0][alr]=av.x; As[alk+1][alr]=av.y;
        As[alk+2][alr]=av.z; As[alk+3][alr]=av.w;
        if(BT){
            Bs[alk+0][alr]=bv.x; Bs[alk+1][alr]=bv.y;
            Bs[alk+2][alr]=bv.z; Bs[alk+3][alr]=bv.w;
        } else {
            *(float4*)&Bs[bkr][bcl] = bv;
        }
        __syncthreads();
        #pragma unroll
        for(int kk=0;kk<8;kk++){
            float4 a0=*(const float4*)&As[kk][ty*8];
            float4 a1=*(const float4*)&As[kk][ty*8+4];
            float4 b0=*(const float4*)&Bs[kk][tx*8];
            float4 b1=*(const float4*)&Bs[kk][tx*8+4];
            float a[8]={a0.x,a0.y,a0.z,a0.w,a1.x,a1.y,a1.z,a1.w};
            float b[8]={b0.x,b0.y,b0.z,b0.w,b1.x,b1.y,b1.z,b1.w};
            #pragma unroll
            for(int i=0;i<8;i++)
                #pragma unroll
                for(int j=0;j<8;j++)
                    acc[i][j] = fmaf(a[i], b[j], acc[i][j]);
        }
    }

    #pragma unroll
    for(int i=0;i<8;i++){
        int m = bm*128 + ty*8 + i;
        long crow = (long)m * N;
        #pragma unroll
        for(int j=0;j<8;j++){
            int n = bn*128 + tx*8 + j;
            if(n < N){
                float v = acc[i][j];
                if(bias)   v += bias[n];
                if(dogelu) v  = gelu_f(v);
                if(Rb)     v += Rb[crow + n];
                Cb[crow + n] = v;
            }
        }
    }
}

// ---------------- LayerNorm (one block per row) ----------------
__global__ void ln_kernel(const float* __restrict__ x, const float* __restrict__ g,
                          const float* __restrict__ b, float* __restrict__ y, int N)
{
    __shared__ float sh[32];
    long base = (long)blockIdx.x * N;
    float s=0.f, ss=0.f;
    for(int c=threadIdx.x;c<N;c+=blockDim.x){
        float v = x[base+c]; s += v; ss += v*v;
    }
    s  = blockReduceSum(s,  sh);
    ss = blockReduceSum(ss, sh);
    float mu  = s  / (float)N;
    float var = ss / (float)N - mu*mu;
    float rs  = rsqrtf(var + 1e-6f);
    for(int c=threadIdx.x;c<N;c+=blockDim.x){
        y[base+c] = (x[base+c]-mu)*rs*g[c] + b[c];
    }
}

// ---------------- softmax over rows of 1024 ----------------
__global__ void softmax1024(float* __restrict__ S)
{
    __shared__ float sh[32];
    long base = (long)blockIdx.x * 1024;
    int tid = threadIdx.x;   // 256
    float v0=S[base+tid], v1=S[base+tid+256], v2=S[base+tid+512], v3=S[base+tid+768];
    float m = fmaxf(fmaxf(v0,v1), fmaxf(v2,v3));
    float M = blockReduceMax(m, sh);
    v0=__expf(v0-M); v1=__expf(v1-M); v2=__expf(v2-M); v3=__expf(v3-M);
    float T = blockReduceSum(v0+v1+v2+v3, sh);
    float inv = 1.f / T;
    S[base+tid]     = v0*inv;
    S[base+tid+256] = v1*inv;
    S[base+tid+512] = v2*inv;
    S[base+tid+768] = v3*inv;
}

// ---------------- RoPE tables ----------------
__global__ void init_rope()
{
    int gid = blockIdx.x*blockDim.x + threadIdx.x;
    if(gid >= IMG_TOK*HD) return;
    int d = gid % HD, t = gid / HD;
    int iw=t&1, ih=(t>>1)&1, bw=(t>>2)&15, bh=t>>6;
    int gh = bh*2+ih, gw = bw*2+iw;
    int dd = d % 36;
    int pos, i;
    if(dd < 18){ i = dd;      pos = gh; }
    else       { i = dd - 18; pos = gw; }
    float inv = powf(10000.0f, -((float)(2*i)/36.0f));
    float ang = (float)pos * inv;
    g_cos[gid] = cosf(ang);
    g_sin[gid] = sinf(ang);
}

// ---------------- patch pos-embed (bilinear interp) ----------------
__global__ void add_pos(float* __restrict__ x, const float* __restrict__ pe)
{
    int gid = blockIdx.x*blockDim.x + threadIdx.x;
    if(gid >= SEQ*HIDDEN) return;
    int j = gid % HIDDEN; int s = gid / HIDDEN;
    int t = s & 1023;
    int iw=t&1, ih=(t>>1)&1, bw=(t>>2)&15, bh=t>>6;
    int gh = bh*2+ih, gw = bw*2+iw;
    double hl = (double)gh*47.0/31.0;
    double wl = (double)gw*47.0/31.0;
    int h0=(int)hl; int h1=min(h0+1,47); float dh=(float)(hl-(double)h0);
    int w0=(int)wl; int w1=min(w0+1,47); float dw=(float)(wl-(double)w0);
    float p00 = pe[(h0*48+w0)*HIDDEN + j];
    float p01 = pe[(h0*48+w1)*HIDDEN + j];
    float p10 = pe[(h1*48+w0)*HIDDEN + j];
    float p11 = pe[(h1*48+w1)*HIDDEN + j];
    float v = (1.f-dh)*((1.f-dw)*p00 + dw*p01) + dh*((1.f-dw)*p10 + dw*p11);
    x[gid] += v;
}

// ---------------- RoPE apply + repack qkv -> per-(image,head) tensors ----------------
__global__ void rope_pack(const float* __restrict__ qkv, float* __restrict__ q2,
                          float* __restrict__ k2, float* __restrict__ v2)
{
    int gid = blockIdx.x*blockDim.x + threadIdx.x;
    if(gid >= SEQ*HEADS*HD) return;
    int d = gid % HD;
    int h = (gid / HD) % HEADS;
    int s = gid / (HD*HEADS);
    int t = s & (IMG_TOK-1);
    int b = s >> 10;
    float c  = g_cos[t*HD + d];
    float sn = g_sin[t*HD + d];
    long base = (long)s*(3*HIDDEN) + h*HD;
    float qd = qkv[base + d];
    float kd = qkv[base + HIDDEN + d];
    int   dp  = (d<36) ? d+36 : d-36;
    float sgn = (d<36) ? -1.f : 1.f;
    float qp = qkv[base + dp];
    float kp = qkv[base + HIDDEN + dp];
    long oi = ((long)(b*HEADS + h)*IMG_TOK + t)*HD + d;
    q2[oi] = (qd*c + sgn*qp*sn) * SCALE_Q;
    k2[oi] =  kd*c + sgn*kp*sn;
    v2[oi] =  qkv[base + 2*HIDDEN + d];
}

// ---------------- attention out repack ----------------
__global__ void unpack_attn(const float* __restrict__ o2, float* __restrict__ attn)
{
    int gid = blockIdx.x*blockDim.x + threadIdx.x;
    if(gid >= SEQ*HEADS*HD) return;
    int d = gid % HD;
    int h = (gid / HD) % HEADS;
    int s = gid / (HD*HEADS);
    int t = s & (IMG_TOK-1);
    int b = s >> 10;
    attn[(long)s*HIDDEN + h*HD + d] =
        o2[((long)(b*HEADS + h)*IMG_TOK + t)*HD + d];
}

// ---------------- host-side launch helpers ----------------
static inline void gemm_bt(const float*A,const float*B,float*C,const float*bias,const float*res,
                           int M,int N,int K,int batch,long sA,long sB,long sC,int dogelu){
    dim3 g((N+127)/128, M/128, batch);
    gemm128<1><<<g,256>>>(A,B,C,bias,res,M,N,K,sA,sB,sC,dogelu);
}
static inline void gemm_nn(const float*A,const float*B,float*C,const float*bias,const float*res,
                           int M,int N,int K,int batch,long sA,long sB,long sC,int dogelu){
    dim3 g((N+127)/128, M/128, batch);
    gemm128<0><<<g,256>>>(A,B,C,bias,res,M,N,K,sA,sB,sC,dogelu);
}

extern "C" void kernel_launch(void* const* d_in, const int* in_sizes, int n_in,
                              void* d_out, int out_size)
{
    const float* pixel   = (const float*)d_in[0];
    const float* patch_w = (const float*)d_in[1];
    const float* patch_b = (const float*)d_in[2];
    const float* pos_e   = (const float*)d_in[3];
    const float* qkv_w   = (const float*)d_in[4];
    const float* qkv_b   = (const float*)d_in[5];
    const float* proj_w  = (const float*)d_in[6];
    const float* proj_b  = (const float*)d_in[7];
    const float* ln1_g   = (const float*)d_in[8];
    const float* ln1_b   = (const float*)d_in[9];
    const float* ln2_g   = (const float*)d_in[10];
    const float* ln2_b   = (const float*)d_in[11];
    const float* fc1_w   = (const float*)d_in[12];
    const float* fc1_b   = (const float*)d_in[13];
    const float* fc2_w   = (const float*)d_in[14];
    const float* fc2_b   = (const float*)d_in[15];
    const float* m_ln_g  = (const float*)d_in[16];
    const float* m_ln_b  = (const float*)d_in[17];
    const float* m_fc1_w = (const float*)d_in[18];
    const float* m_fc1_b = (const float*)d_in[19];
    const float* m_fc2_w = (const float*)d_in[20];
    const float* m_fc2_b = (const float*)d_in[21];
    const float* ds_ln_g = (const float*)d_in[22];
    const float* ds_ln_b = (const float*)d_in[23];
    const float* ds_fc1_w= (const float*)d_in[24];
    const float* ds_fc1_b= (const float*)d_in[25];
    const float* ds_fc2_w= (const float*)d_in[26];
    const float* ds_fc2_b= (const float*)d_in[27];
    float* out = (float*)d_out;

    float *px,*pxn,*pqkv,*pq2,*pk2,*pv2,*psc,*po2,*pattn,*ph,*pmh,*pmf;
    cudaGetSymbolAddress((void**)&px,   g_x);
    cudaGetSymbolAddress((void**)&pxn,  g_xn);
    cudaGetSymbolAddress((void**)&pqkv, g_qkv);
    cudaGetSymbolAddress((void**)&pq2,  g_q2);
    cudaGetSymbolAddress((void**)&pk2,  g_k2);
    cudaGetSymbolAddress((void**)&pv2,  g_v2);
    cudaGetSymbolAddress((void**)&psc,  g_sc);
    cudaGetSymbolAddress((void**)&po2,  g_o2);
    cudaGetSymbolAddress((void**)&pattn,g_attn);
    cudaGetSymbolAddress((void**)&ph,   g_h);
    cudaGetSymbolAddress((void**)&pmh,  g_mh);
    cudaGetSymbolAddress((void**)&pmf,  g_mf);

    const int EW = 256;
    init_rope<<<(IMG_TOK*HD + EW-1)/EW, EW>>>();

    // patch embed + pos embed
    gemm_bt(pixel, patch_w, px, patch_b, nullptr, SEQ, HIDDEN, PATCHD, 1, 0,0,0, 0);
    add_pos<<<(SEQ*HIDDEN + EW-1)/EW, EW>>>(px, pos_e);

    const int NQH = SEQ*HEADS*HD;
    for(int i=0;i<DEPTH;i++){
        // attention block
        ln_kernel<<<SEQ,256>>>(px, ln1_g+(long)i*HIDDEN, ln1_b+(long)i*HIDDEN, pxn, HIDDEN);
        gemm_bt(pxn, qkv_w+(long)i*3*HIDDEN*HIDDEN, pqkv, qkv_b+(long)i*3*HIDDEN, nullptr,
                SEQ, 3*HIDDEN, HIDDEN, 1, 0,0,0, 0);
        rope_pack<<<(NQH + EW-1)/EW, EW>>>(pqkv, pq2, pk2, pv2);
        // S = Q @ K^T   (batched over 64 (image,head) pairs)
        gemm_bt(pq2, pk2, psc, nullptr, nullptr,
                IMG_TOK, IMG_TOK, HD, NBH,
                (long)IMG_TOK*HD, (long)IMG_TOK*HD, (long)IMG_TOK*IMG_TOK, 0);
        softmax1024<<<NBH*IMG_TOK, 256>>>(psc);
        // O = P @ V
        gemm_nn(psc, pv2, po2, nullptr, nullptr,
                IMG_TOK, HD, IMG_TOK, NBH,
                (long)IMG_TOK*IMG_TOK, (long)IMG_TOK*HD, (long)IMG_TOK*HD, 0);
        unpack_attn<<<(NQH + EW-1)/EW, EW>>>(po2, pattn);
        // proj (+residual into x)
        gemm_bt(pattn, proj_w+(long)i*HIDDEN*HIDDEN, px, proj_b+(long)i*HIDDEN, px,
                SEQ, HIDDEN, HIDDEN, 1, 0,0,0, 0);

        // MLP block
        ln_kernel<<<SEQ,256>>>(px, ln2_g+(long)i*HIDDEN, ln2_b+(long)i*HIDDEN, pxn, HIDDEN);
        gemm_bt(pxn, fc1_w+(long)i*INTER*HIDDEN, ph, fc1_b+(long)i*INTER, nullptr,
                SEQ, INTER, HIDDEN, 1, 0,0,0, 1);
        gemm_bt(ph, fc2_w+(long)i*HIDDEN*INTER, px, fc2_b+(long)i*HIDDEN, px,
                SEQ, HIDDEN, INTER, 1, 0,0,0, 0);

        // deepstack mergers at layers 2 and 4 (post-LN over MERGED)
        if(i==2 || i==4){
            int j = (i==2) ? 0 : 1;
            ln_kernel<<<1024,256>>>(px, ds_ln_g+(long)j*MERGED, ds_ln_b+(long)j*MERGED, pmh, MERGED);
            gemm_bt(pmh, ds_fc1_w+(long)j*MERGED*MERGED, pmf, ds_fc1_b+(long)j*MERGED, nullptr,
                    1024, MERGED, MERGED, 1, 0,0,0, 1);
            gemm_bt(pmf, ds_fc2_w+(long)j*OUTH*MERGED, out+(long)(1+j)*1024*OUTH,
                    ds_fc2_b+(long)j*OUTH, nullptr,
                    1024, OUTH, MERGED, 1, 0,0,0, 0);
        }
    }

    // final merger (pre-LN over HIDDEN, then reshape to [1024,4608])
    ln_kernel<<<SEQ,256>>>(px, m_ln_g, m_ln_b, pmh, HIDDEN);
    gemm_bt(pmh, m_fc1_w, pmf, m_fc1_b, nullptr, 1024, MERGED, MERGED, 1, 0,0,0, 1);
    gemm_bt(pmf, m_fc2_w, out, m_fc2_b, nullptr, 1024, OUTH, MERGED, 1, 0,0,0, 0);
}

// round 2
// speedup vs baseline: 2.7698x; 2.7698x over previous
#include <cuda_runtime.h>
#include <math.h>
#include <stdint.h>

// ---------------- problem constants ----------------
#define SEQ      4096
#define HIDDEN   1152
#define HEADS    16
#define HD       72
#define INTER    4304
#define DEPTH    6
#define MERGED   4608
#define OUTH     2048
#define PATCHD   1536
#define IMG_TOK  1024
#define NBH      64
#define SCALE_Q  0.11785113019775793f

// ---------------- device scratch ----------------
__device__ float g_x   [SEQ*HIDDEN];
__device__ float g_xn  [SEQ*HIDDEN];
__device__ float g_qkv [SEQ*3*HIDDEN];
__device__ float g_q2  [NBH*IMG_TOK*HD];
__device__ float g_k2  [NBH*IMG_TOK*HD];
__device__ float g_v2  [NBH*IMG_TOK*HD];
__device__ float g_sc  [67108864];
__device__ float g_o2  [NBH*IMG_TOK*HD];
__device__ float g_attn[SEQ*HIDDEN];
__device__ float g_h   [SEQ*INTER];
__device__ float g_mh  [SEQ*HIDDEN];
__device__ float g_mf  [1024*MERGED];
__device__ float g_cos [IMG_TOK*HD];
__device__ float g_sin [IMG_TOK*HD];

// ---------------- helpers ----------------
__device__ __forceinline__ float gelu_f(float x){
    float x3 = x*x*x;
    return 0.5f*x*(1.0f + tanhf(0.7978845608028654f*(x + 0.044715f*x3)));
}

__device__ __forceinline__ uint32_t tf32r(float x){
    uint32_t u;
    asm("cvt.rna.tf32.f32 %0, %1;" : "=r"(u) : "f"(x));
    return u;
}

__device__ __forceinline__ void mma8(float* c, const uint32_t* a, const uint32_t* b){
    asm volatile("mma.sync.aligned.m16n8k8.row.col.f32.tf32.tf32.f32 "
        "{%0,%1,%2,%3},{%4,%5,%6,%7},{%8,%9},{%0,%1,%2,%3};"
        : "+f"(c[0]),"+f"(c[1]),"+f"(c[2]),"+f"(c[3])
        : "r"(a[0]),"r"(a[1]),"r"(a[2]),"r"(a[3]),"r"(b[0]),"r"(b[1]));
}

__device__ __forceinline__ float blockReduceSum(float v, float* sh){
    int tid = threadIdx.x;
    __syncthreads();
    #pragma unroll
    for(int o=16;o>0;o>>=1) v += __shfl_xor_sync(0xffffffffu, v, o);
    if((tid&31)==0) sh[tid>>5] = v;
    __syncthreads();
    if(tid < 32){
        float r = (tid < (int)(blockDim.x>>5)) ? sh[tid] : 0.f;
        #pragma unroll
        for(int o=16;o>0;o>>=1) r += __shfl_xor_sync(0xffffffffu, r, o);
        if(tid==0) sh[0] = r;
    }
    __syncthreads();
    return sh[0];
}

__device__ __forceinline__ float blockReduceMax(float v, float* sh){
    int tid = threadIdx.x;
    __syncthreads();
    #pragma unroll
    for(int o=16;o>0;o>>=1) v = fmaxf(v, __shfl_xor_sync(0xffffffffu, v, o));
    if((tid&31)==0) sh[tid>>5] = v;
    __syncthreads();
    if(tid < 32){
        float r = (tid < (int)(blockDim.x>>5)) ? sh[tid] : -3.4e38f;
        #pragma unroll
        for(int o=16;o>0;o>>=1) r = fmaxf(r, __shfl_xor_sync(0xffffffffu, r, o));
        if(tid==0) sh[0] = r;
    }
    __syncthreads();
    return sh[0];
}

// ---------------- TF32 tensor-core GEMM ----------------
// C = A @ op(B) + bias [+gelu] [+res]
// BT=1: B is [N,K] row-major. BT=0: B is [K,N] row-major.
// A [M,K] row-major, M%128==0, K%8==0, N%4==0 (all true in this model).
// Block tile 128x128, K-tile 32, double-buffered smem, 8 warps of 32x64.
#define AST 36          // A/B(BT) smem row stride (floats)
#define BNNST 136       // B(NN) smem row stride
#define ABUF 4608       // 128*36
#define SMEM_FLOATS (4*4608)
#define SMEM_BYTES  (SMEM_FLOATS*4)

template<int BT>
__global__ __launch_bounds__(256)
void gemm_tc(const float* __restrict__ A, const float* __restrict__ B,
             float* __restrict__ C, const float* __restrict__ bias,
             const float* __restrict__ res,
             int M, int N, int K,
             long sA, long sB, long sC, int dogelu)
{
    extern __shared__ float sm[];
    float* Asm[2] = { sm,        sm + ABUF   };
    float* Bsm[2] = { sm + 2*ABUF, sm + 3*ABUF };

    const int tid  = threadIdx.x;
    const int lane = tid & 31, warp = tid >> 5;
    const int g = lane >> 2, t = lane & 3;
    const int wm = warp >> 1, wn = warp & 1;
    const int m0 = wm*32, n0 = wn*64;

    const int bn = blockIdx.x, bm = blockIdx.y, bz = blockIdx.z;
    const float* Ab = A + (long)bz*sA;
    const float* Bb = B + (long)bz*sB;
    float*       Cb = C + (long)bz*sC;
    const float* Rb = res ? (res + (long)bz*sC) : (const float*)0;

    float acc[2][8][4];
    #pragma unroll
    for(int i=0;i<2;i++)
        #pragma unroll
        for(int j=0;j<8;j++)
            #pragma unroll
            for(int q=0;q<4;q++) acc[i][j][q]=0.f;

    // loader indices
    const int alr = (tid>>3);          // 0..31  (+r*32)
    const int alk = (tid&7)*4;         // 0..28
    const int nlr = (tid>>5);          // 0..7   (+r*8)  NN k-row
    const int nlc = (tid&31)*4;        // 0..124 NN col

    const int NT = (K+31)/32;
    float4 ar[4], br[4];

    // prefetch tile 0
    {
        int k0 = 0;
        #pragma unroll
        for(int r=0;r<4;r++){
            int row = alr + r*32, k = k0 + alk;
            ar[r] = (k<K) ? *(const float4*)(Ab + (long)(bm*128+row)*K + k)
                          : make_float4(0,0,0,0);
            if(BT){
                int brow = bn*128 + row;
                br[r] = (brow<N && k<K) ? *(const float4*)(Bb + (long)brow*K + k)
                                        : make_float4(0,0,0,0);
            } else {
                int kk = k0 + nlr + r*8, col = bn*128 + nlc;
                br[r] = (kk<K && col<N) ? *(const float4*)(Bb + (long)kk*N + col)
                                        : make_float4(0,0,0,0);
            }
        }
        #pragma unroll
        for(int r=0;r<4;r++){
            int row = alr + r*32;
            uint4 ua; ua.x=tf32r(ar[r].x); ua.y=tf32r(ar[r].y); ua.z=tf32r(ar[r].z); ua.w=tf32r(ar[r].w);
            *(uint4*)&Asm[0][row*AST + alk] = ua;
            uint4 ub; ub.x=tf32r(br[r].x); ub.y=tf32r(br[r].y); ub.z=tf32r(br[r].z); ub.w=tf32r(br[r].w);
            if(BT) *(uint4*)&Bsm[0][row*AST + alk] = ub;
            else   *(uint4*)&Bsm[0][(nlr + r*8)*BNNST + nlc] = ub;
        }
    }
    __syncthreads();

    for(int kt=0; kt<NT; kt++){
        // prefetch next tile into regs
        if(kt+1 < NT){
            int k0 = (kt+1)*32;
            #pragma unroll
            for(int r=0;r<4;r++){
                int row = alr + r*32, k = k0 + alk;
                ar[r] = (k<K) ? *(const float4*)(Ab + (long)(bm*128+row)*K + k)
                              : make_float4(0,0,0,0);
                if(BT){
                    int brow = bn*128 + row;
                    br[r] = (brow<N && k<K) ? *(const float4*)(Bb + (long)brow*K + k)
                                            : make_float4(0,0,0,0);
                } else {
                    int kk = k0 + nlr + r*8, col = bn*128 + nlc;
                    br[r] = (kk<K && col<N) ? *(const float4*)(Bb + (long)kk*N + col)
                                            : make_float4(0,0,0,0);
                }
            }
        }

        // compute current buffer
        {
            const uint32_t* Au = (const uint32_t*)Asm[kt&1];
            const uint32_t* Bu = (const uint32_t*)Bsm[kt&1];
            #pragma unroll
            for(int s=0;s<4;s++){
                uint32_t af[2][4];
                #pragma unroll
                for(int mt=0;mt<2;mt++){
                    int rbase = m0 + mt*16;
                    af[mt][0] = Au[(rbase+g  )*AST + s*8 + t    ];
                    af[mt][1] = Au[(rbase+8+g)*AST + s*8 + t    ];
                    af[mt][2] = Au[(rbase+g  )*AST + s*8 + t + 4];
                    af[mt][3] = Au[(rbase+8+g)*AST + s*8 + t + 4];
                }
                uint32_t bf[8][2];
                #pragma unroll
                for(int nt=0;nt<8;nt++){
                    if(BT){
                        bf[nt][0] = Bu[(n0+nt*8+g)*AST + s*8 + t    ];
                        bf[nt][1] = Bu[(n0+nt*8+g)*AST + s*8 + t + 4];
                    } else {
                        bf[nt][0] = Bu[(s*8+t    )*BNNST + n0 + nt*8 + g];
                        bf[nt][1] = Bu[(s*8+t + 4)*BNNST + n0 + nt*8 + g];
                    }
                }
                #pragma unroll
                for(int mt=0;mt<2;mt++)
                    #pragma unroll
                    for(int nt=0;nt<8;nt++)
                        mma8(acc[mt][nt], af[mt], bf[nt]);
            }
        }

        // store next tile to other buffer
        if(kt+1 < NT){
            float* An = Asm[(kt+1)&1];
            float* Bn = Bsm[(kt+1)&1];
            #pragma unroll
            for(int r=0;r<4;r++){
                int row = alr + r*32;
                uint4 ua; ua.x=tf32r(ar[r].x); ua.y=tf32r(ar[r].y); ua.z=tf32r(ar[r].z); ua.w=tf32r(ar[r].w);
                *(uint4*)&An[row*AST + alk] = ua;
                uint4 ub; ub.x=tf32r(br[r].x); ub.y=tf32r(br[r].y); ub.z=tf32r(br[r].z); ub.w=tf32r(br[r].w);
                if(BT) *(uint4*)&Bn[row*AST + alk] = ub;
                else   *(uint4*)&Bn[(nlr + r*8)*BNNST + nlc] = ub;
            }
        }
        __syncthreads();
    }

    // epilogue
    #pragma unroll
    for(int mt=0;mt<2;mt++){
        int r0 = bm*128 + m0 + mt*16 + g;
        int r1 = r0 + 8;
        #pragma unroll
        for(int nt=0;nt<8;nt++){
            int col = bn*128 + n0 + nt*8 + t*2;
            if(col < N){
                float v0 = acc[mt][nt][0], v1 = acc[mt][nt][1];
                float v2 = acc[mt][nt][2], v3 = acc[mt][nt][3];
                if(bias){ float b0=bias[col], b1=bias[col+1]; v0+=b0; v1+=b1; v2+=b0; v3+=b1; }
                if(dogelu){ v0=gelu_f(v0); v1=gelu_f(v1); v2=gelu_f(v2); v3=gelu_f(v3); }
                long i0 = (long)r0*N + col, i1 = (long)r1*N + col;
                if(Rb){ v0+=Rb[i0]; v1+=Rb[i0+1]; v2+=Rb[i1]; v3+=Rb[i1+1]; }
                Cb[i0]=v0; Cb[i0+1]=v1; Cb[i1]=v2; Cb[i1+1]=v3;
            }
        }
    }
}

// ---------------- LayerNorm ----------------
__global__ void ln_kernel(const float* __restrict__ x, const float* __restrict__ g,
                          const float* __restrict__ b, float* __restrict__ y, int N)
{
    __shared__ float sh[32];
    long base = (long)blockIdx.x * N;
    float s=0.f, ss=0.f;
    for(int c=threadIdx.x;c<N;c+=blockDim.x){
        float v = x[base+c]; s += v; ss += v*v;
    }
    s  = blockReduceSum(s,  sh);
    ss = blockReduceSum(ss, sh);
    float mu  = s  / (float)N;
    float var = ss / (float)N - mu*mu;
    float rs  = rsqrtf(var + 1e-6f);
    for(int c=threadIdx.x;c<N;c+=blockDim.x){
        y[base+c] = (x[base+c]-mu)*rs*g[c] + b[c];
    }
}

// ---------------- softmax over rows of 1024 ----------------
__global__ void softmax1024(float* __restrict__ S)
{
    __shared__ float sh[32];
    long base = (long)blockIdx.x * 1024;
    int tid = threadIdx.x;
    float v0=S[base+tid], v1=S[base+tid+256], v2=S[base+tid+512], v3=S[base+tid+768];
    float m = fmaxf(fmaxf(v0,v1), fmaxf(v2,v3));
    float M = blockReduceMax(m, sh);
    v0=__expf(v0-M); v1=__expf(v1-M); v2=__expf(v2-M); v3=__expf(v3-M);
    float T = blockReduceSum(v0+v1+v2+v3, sh);
    float inv = 1.f / T;
    S[base+tid]     = v0*inv;
    S[base+tid+256] = v1*inv;
    S[base+tid+512] = v2*inv;
    S[base+tid+768] = v3*inv;
}

// ---------------- RoPE tables ----------------
__global__ void init_rope()
{
    int gid = blockIdx.x*blockDim.x + threadIdx.x;
    if(gid >= IMG_TOK*HD) return;
    int d = gid % HD, tt = gid / HD;
    int iw=tt&1, ih=(tt>>1)&1, bw=(tt>>2)&15, bh=tt>>6;
    int gh = bh*2+ih, gw = bw*2+iw;
    int dd = d % 36;
    int pos, i;
    if(dd < 18){ i = dd;      pos = gh; }
    else       { i = dd - 18; pos = gw; }
    float inv = powf(10000.0f, -((float)(2*i)/36.0f));
    float ang = (float)pos * inv;
    g_cos[gid] = cosf(ang);
    g_sin[gid] = sinf(ang);
}

// ---------------- pos-embed bilinear add ----------------
__global__ void add_pos(float* __restrict__ x, const float* __restrict__ pe)
{
    int gid = blockIdx.x*blockDim.x + threadIdx.x;
    if(gid >= SEQ*HIDDEN) return;
    int j = gid % HIDDEN; int s = gid / HIDDEN;
    int tt = s & 1023;
    int iw=tt&1, ih=(tt>>1)&1, bw=(tt>>2)&15, bh=tt>>6;
    int gh = bh*2+ih, gw = bw*2+iw;
    double hl = (double)gh*47.0/31.0;
    double wl = (double)gw*47.0/31.0;
    int h0=(int)hl; int h1=min(h0+1,47); float dh=(float)(hl-(double)h0);
    int w0=(int)wl; int w1=min(w0+1,47); float dw=(float)(wl-(double)w0);
    float p00 = pe[(h0*48+w0)*HIDDEN + j];
    float p01 = pe[(h0*48+w1)*HIDDEN + j];
    float p10 = pe[(h1*48+w0)*HIDDEN + j];
    float p11 = pe[(h1*48+w1)*HIDDEN + j];
    float v = (1.f-dh)*((1.f-dw)*p00 + dw*p01) + dh*((1.f-dw)*p10 + dw*p11);
    x[gid] += v;
}

// ---------------- RoPE apply + repack ----------------
__global__ void rope_pack(const float* __restrict__ qkv, float* __restrict__ q2,
                          float* __restrict__ k2, float* __restrict__ v2)
{
    int gid = blockIdx.x*blockDim.x + threadIdx.x;
    if(gid >= SEQ*HEADS*HD) return;
    int d = gid % HD;
    int h = (gid / HD) % HEADS;
    int s = gid / (HD*HEADS);
    int tt = s & (IMG_TOK-1);
    int b = s >> 10;
    float c  = g_cos[tt*HD + d];
    float sn = g_sin[tt*HD + d];
    long base = (long)s*(3*HIDDEN) + h*HD;
    float qd = qkv[base + d];
    float kd = qkv[base + HIDDEN + d];
    int   dp  = (d<36) ? d+36 : d-36;
    float sgn = (d<36) ? -1.f : 1.f;
    float qp = qkv[base + dp];
    float kp = qkv[base + HIDDEN + dp];
    long oi = ((long)(b*HEADS + h)*IMG_TOK + tt)*HD + d;
    q2[oi] = (qd*c + sgn*qp*sn) * SCALE_Q;
    k2[oi] =  kd*c + sgn*kp*sn;
    v2[oi] =  qkv[base + 2*HIDDEN + d];
}

// ---------------- attention out repack ----------------
__global__ void unpack_attn(const float* __restrict__ o2, float* __restrict__ attn)
{
    int gid = blockIdx.x*blockDim.x + threadIdx.x;
    if(gid >= SEQ*HEADS*HD) return;
    int d = gid % HD;
    int h = (gid / HD) % HEADS;
    int s = gid / (HD*HEADS);
    int tt = s & (IMG_TOK-1);
    int b = s >> 10;
    attn[(long)s*HIDDEN + h*HD + d] =
        o2[((long)(b*HEADS + h)*IMG_TOK + tt)*HD + d];
}

// ---------------- host-side launch helpers ----------------
static inline void gemm_bt(const float*A,const float*B,float*C,const float*bias,const float*res,
                           int M,int N,int K,int batch,long sA,long sB,long sC,int dogelu){
    dim3 g((N+127)/128, M/128, batch);
    gemm_tc<1><<<g,256,SMEM_BYTES>>>(A,B,C,bias,res,M,N,K,sA,sB,sC,dogelu);
}
static inline void gemm_nn(const float*A,const float*B,float*C,const float*bias,const float*res,
                           int M,int N,int K,int batch,long sA,long sB,long sC,int dogelu){
    dim3 g((N+127)/128, M/128, batch);
    gemm_tc<0><<<g,256,SMEM_BYTES>>>(A,B,C,bias,res,M,N,K,sA,sB,sC,dogelu);
}

extern "C" void kernel_launch(void* const* d_in, const int* in_sizes, int n_in,
                              void* d_out, int out_size)
{
    const float* pixel   = (const float*)d_in[0];
    const float* patch_w = (const float*)d_in[1];
    const float* patch_b = (const float*)d_in[2];
    const float* pos_e   = (const float*)d_in[3];
    const float* qkv_w   = (const float*)d_in[4];
    const float* qkv_b   = (const float*)d_in[5];
    const float* proj_w  = (const float*)d_in[6];
    const float* proj_b  = (const float*)d_in[7];
    const float* ln1_g   = (const float*)d_in[8];
    const float* ln1_b   = (const float*)d_in[9];
    const float* ln2_g   = (const float*)d_in[10];
    const float* ln2_b   = (const float*)d_in[11];
    const float* fc1_w   = (const float*)d_in[12];
    const float* fc1_b   = (const float*)d_in[13];
    const float* fc2_w   = (const float*)d_in[14];
    const float* fc2_b   = (const float*)d_in[15];
    const float* m_ln_g  = (const float*)d_in[16];
    const float* m_ln_b  = (const float*)d_in[17];
    const float* m_fc1_w = (const float*)d_in[18];
    const float* m_fc1_b = (const float*)d_in[19];
    const float* m_fc2_w = (const float*)d_in[20];
    const float* m_fc2_b = (const float*)d_in[21];
    const float* ds_ln_g = (const float*)d_in[22];
    const float* ds_ln_b = (const float*)d_in[23];
    const float* ds_fc1_w= (const float*)d_in[24];
    const float* ds_fc1_b= (const float*)d_in[25];
    const float* ds_fc2_w= (const float*)d_in[26];
    const float* ds_fc2_b= (const float*)d_in[27];
    float* out = (float*)d_out;

    cudaFuncSetAttribute(gemm_tc<1>, cudaFuncAttributeMaxDynamicSharedMemorySize, SMEM_BYTES);
    cudaFuncSetAttribute(gemm_tc<0>, cudaFuncAttributeMaxDynamicSharedMemorySize, SMEM_BYTES);

    float *px,*pxn,*pqkv,*pq2,*pk2,*pv2,*psc,*po2,*pattn,*ph,*pmh,*pmf;
    cudaGetSymbolAddress((void**)&px,   g_x);
    cudaGetSymbolAddress((void**)&pxn,  g_xn);
    cudaGetSymbolAddress((void**)&pqkv, g_qkv);
    cudaGetSymbolAddress((void**)&pq2,  g_q2);
    cudaGetSymbolAddress((void**)&pk2,  g_k2);
    cudaGetSymbolAddress((void**)&pv2,  g_v2);
    cudaGetSymbolAddress((void**)&psc,  g_sc);
    cudaGetSymbolAddress((void**)&po2,  g_o2);
    cudaGetSymbolAddress((void**)&pattn,g_attn);
    cudaGetSymbolAddress((void**)&ph,   g_h);
    cudaGetSymbolAddress((void**)&pmh,  g_mh);
    cudaGetSymbolAddress((void**)&pmf,  g_mf);

    const int EW = 256;
    init_rope<<<(IMG_TOK*HD + EW-1)/EW, EW>>>();

    gemm_bt(pixel, patch_w, px, patch_b, nullptr, SEQ, HIDDEN, PATCHD, 1, 0,0,0, 0);
    add_pos<<<(SEQ*HIDDEN + EW-1)/EW, EW>>>(px, pos_e);

    const int NQH = SEQ*HEADS*HD;
    for(int i=0;i<DEPTH;i++){
        ln_kernel<<<SEQ,256>>>(px, ln1_g+(long)i*HIDDEN, ln1_b+(long)i*HIDDEN, pxn, HIDDEN);
        gemm_bt(pxn, qkv_w+(long)i*3*HIDDEN*HIDDEN, pqkv, qkv_b+(long)i*3*HIDDEN, nullptr,
                SEQ, 3*HIDDEN, HIDDEN, 1, 0,0,0, 0);
        rope_pack<<<(NQH + EW-1)/EW, EW>>>(pqkv, pq2, pk2, pv2);
        gemm_bt(pq2, pk2, psc, nullptr, nullptr,
                IMG_TOK, IMG_TOK, HD, NBH,
                (long)IMG_TOK*HD, (long)IMG_TOK*HD, (long)IMG_TOK*IMG_TOK, 0);
        softmax1024<<<NBH*IMG_TOK, 256>>>(psc);
        gemm_nn(psc, pv2, po2, nullptr, nullptr,
                IMG_TOK, HD, IMG_TOK, NBH,
                (long)IMG_TOK*IMG_TOK, (long)IMG_TOK*HD, (long)IMG_TOK*HD, 0);
        unpack_attn<<<(NQH + EW-1)/EW, EW>>>(po2, pattn);
        gemm_bt(pattn, proj_w+(long)i*HIDDEN*HIDDEN, px, proj_b+(long)i*HIDDEN, px,
                SEQ, HIDDEN, HIDDEN, 1, 0,0,0, 0);

        ln_kernel<<<SEQ,256>>>(px, ln2_g+(long)i*HIDDEN, ln2_b+(long)i*HIDDEN, pxn, HIDDEN);
        gemm_bt(pxn, fc1_w+(long)i*INTER*HIDDEN, ph, fc1_b+(long)i*INTER, nullptr,
                SEQ, INTER, HIDDEN, 1, 0,0,0, 1);
        gemm_bt(ph, fc2_w+(long)i*HIDDEN*INTER, px, fc2_b+(long)i*HIDDEN, px,
                SEQ, HIDDEN, INTER, 1, 0,0,0, 0);

        if(i==2 || i==4){
            int j = (i==2) ? 0 : 1;
            ln_kernel<<<1024,256>>>(px, ds_ln_g+(long)j*MERGED, ds_ln_b+(long)j*MERGED, pmh, MERGED);
            gemm_bt(pmh, ds_fc1_w+(long)j*MERGED*MERGED, pmf, ds_fc1_b+(long)j*MERGED, nullptr,
                    1024, MERGED, MERGED, 1, 0,0,0, 1);
            gemm_bt(pmf, ds_fc2_w+(long)j*OUTH*MERGED, out+(long)(1+j)*1024*OUTH,
                    ds_fc2_b+(long)j*OUTH, nullptr,
                    1024, OUTH, MERGED, 1, 0,0,0, 0);
        }
    }

    ln_kernel<<<SEQ,256>>>(px, m_ln_g, m_ln_b, pmh, HIDDEN);
    gemm_bt(pmh, m_fc1_w, pmf, m_fc1_b, nullptr, 1024, MERGED, MERGED, 1, 0,0,0, 1);
    gemm_bt(pmf, m_fc2_w, out, m_fc2_b, nullptr, 1024, OUTH, MERGED, 1, 0,0,0, 0);
}

// round 4
// speedup vs baseline: 4.0687x; 1.4690x over previous
#include <cuda_runtime.h>
#include <cuda_fp16.h>
#include <math.h>
#include <stdint.h>

// ---------------- problem constants ----------------
#define SEQ      4096
#define HIDDEN   1152
#define HEADS    16
#define HD       72
#define INTER    4304
#define DEPTH    6
#define MERGED   4608
#define OUTH     2048
#define PATCHD   1536
#define IMG_TOK  1024
#define NBH      64
#define SCALE_Q  0.11785113019775793f

// ---------------- device scratch ----------------
__device__ float g_x   [SEQ*HIDDEN];
__device__ float g_xn  [SEQ*HIDDEN];
__device__ float g_qkv [SEQ*3*HIDDEN];
__device__ float g_q2  [NBH*IMG_TOK*HD];
__device__ float g_k2  [NBH*IMG_TOK*HD];
__device__ float g_v2t [NBH*HD*IMG_TOK];     // V transposed: [bh][d][t]
__device__ float g_sc  [67108864];
__device__ float g_o2  [NBH*IMG_TOK*HD];
__device__ float g_attn[SEQ*HIDDEN];
__device__ float g_h   [SEQ*INTER];
__device__ float g_mh  [SEQ*HIDDEN];
__device__ float g_mf  [1024*MERGED];
__device__ float g_cos [IMG_TOK*HD];
__device__ float g_sin [IMG_TOK*HD];

// ---------------- helpers ----------------
__device__ __forceinline__ float gelu_f(float x){
    float x3 = x*x*x;
    return 0.5f*x*(1.0f + tanhf(0.7978845608028654f*(x + 0.044715f*x3)));
}

__device__ __forceinline__ uint32_t h2u(float a, float b){
    __half2 h = __floats2half2_rn(a, b);
    return *(uint32_t*)&h;
}

__device__ __forceinline__ void mma16(float* c, const uint32_t* a, const uint32_t* b){
    asm volatile("mma.sync.aligned.m16n8k16.row.col.f32.f16.f16.f32 "
        "{%0,%1,%2,%3},{%4,%5,%6,%7},{%8,%9},{%0,%1,%2,%3};"
        : "+f"(c[0]),"+f"(c[1]),"+f"(c[2]),"+f"(c[3])
        : "r"(a[0]),"r"(a[1]),"r"(a[2]),"r"(a[3]),"r"(b[0]),"r"(b[1]));
}

__device__ __forceinline__ float blockReduceSum(float v, float* sh){
    int tid = threadIdx.x;
    __syncthreads();
    #pragma unroll
    for(int o=16;o>0;o>>=1) v += __shfl_xor_sync(0xffffffffu, v, o);
    if((tid&31)==0) sh[tid>>5] = v;
    __syncthreads();
    if(tid < 32){
        float r = (tid < (int)(blockDim.x>>5)) ? sh[tid] : 0.f;
        #pragma unroll
        for(int o=16;o>0;o>>=1) r += __shfl_xor_sync(0xffffffffu, r, o);
        if(tid==0) sh[0] = r;
    }
    __syncthreads();
    return sh[0];
}

__device__ __forceinline__ float blockReduceMax(float v, float* sh){
    int tid = threadIdx.x;
    __syncthreads();
    #pragma unroll
    for(int o=16;o>0;o>>=1) v = fmaxf(v, __shfl_xor_sync(0xffffffffu, v, o));
    if((tid&31)==0) sh[tid>>5] = v;
    __syncthreads();
    if(tid < 32){
        float r = (tid < (int)(blockDim.x>>5)) ? sh[tid] : -3.4e38f;
        #pragma unroll
        for(int o=16;o>0;o>>=1) r = fmaxf(r, __shfl_xor_sync(0xffffffffu, r, o));
        if(tid==0) sh[0] = r;
    }
    __syncthreads();
    return sh[0];
}

// ---------------- FP16 tensor-core GEMM (BT form only) ----------------
// C[M,N] = A[M,K] @ B[N,K]^T + bias [+gelu] [+res]
// A [M,K] f32 row-major, B [N,K] f32 row-major; converted to fp16 in the loader.
// M%128==0, K%4==0. N arbitrary (guarded). Accumulate fp32.
// Block tile 128x128, K-tile 32, double-buffered smem, 8 warps of 32x64.
#define HST 20     // smem row stride in uint32 (half2) units; 16 used + 4 pad

__global__ __launch_bounds__(256)
void gemm_h(const float* __restrict__ A, const float* __restrict__ B,
            float* __restrict__ C, const float* __restrict__ bias,
            const float* __restrict__ res,
            int M, int N, int K,
            long sA, long sB, long sC, int dogelu)
{
    __shared__ uint32_t As[2][128*HST];
    __shared__ uint32_t Bs[2][128*HST];

    const int tid  = threadIdx.x;
    const int lane = tid & 31, warp = tid >> 5;
    const int g = lane >> 2, t = lane & 3;
    const int wm = warp >> 1, wn = warp & 1;
    const int m0 = wm*32, n0 = wn*64;

    const int bn = blockIdx.x, bm = blockIdx.y, bz = blockIdx.z;
    const float* Ab = A + (long)bz*sA;
    const float* Bb = B + (long)bz*sB;
    float*       Cb = C + (long)bz*sC;
    const float* Rb = res ? (res + (long)bz*sC) : (const float*)0;

    float acc[2][8][4];
    #pragma unroll
    for(int i=0;i<2;i++)
        #pragma unroll
        for(int j=0;j<8;j++)
            #pragma unroll
            for(int q=0;q<4;q++) acc[i][j][q]=0.f;

    // loader indices: each thread loads 4 rows (stride 32), one float4 per row per tile
    const int alr = tid >> 3;          // 0..31  (+r*32)
    const int aq  = tid & 7;           // float4 index within 32-k tile
    const int alk = aq * 4;            // k offset 0..28

    const int NT = (K+31)/32;
    float4 ar[4], br[4];

    // prefetch tile 0
    {
        #pragma unroll
        for(int r=0;r<4;r++){
            int row = alr + r*32, k = alk;
            ar[r] = (k<K) ? *(const float4*)(Ab + (long)(bm*128+row)*K + k)
                          : make_float4(0,0,0,0);
            int brow = bn*128 + row;
            br[r] = (brow<N && k<K) ? *(const float4*)(Bb + (long)brow*K + k)
                                    : make_float4(0,0,0,0);
        }
        #pragma unroll
        for(int r=0;r<4;r++){
            int row = alr + r*32;
            As[0][row*HST + aq*2    ] = h2u(ar[r].x, ar[r].y);
            As[0][row*HST + aq*2 + 1] = h2u(ar[r].z, ar[r].w);
            Bs[0][row*HST + aq*2    ] = h2u(br[r].x, br[r].y);
            Bs[0][row*HST + aq*2 + 1] = h2u(br[r].z, br[r].w);
        }
    }
    __syncthreads();

    for(int kt=0; kt<NT; kt++){
        if(kt+1 < NT){
            int k0 = (kt+1)*32;
            #pragma unroll
            for(int r=0;r<4;r++){
                int row = alr + r*32, k = k0 + alk;
                ar[r] = (k<K) ? *(const float4*)(Ab + (long)(bm*128+row)*K + k)
                              : make_float4(0,0,0,0);
                int brow = bn*128 + row;
                br[r] = (brow<N && k<K) ? *(const float4*)(Bb + (long)brow*K + k)
                                        : make_float4(0,0,0,0);
            }
        }

        // compute current buffer: 2 k-steps of 16
        {
            const uint32_t* Au = As[kt&1];
            const uint32_t* Bu = Bs[kt&1];
            #pragma unroll
            for(int s=0;s<2;s++){
                uint32_t af[2][4];
                #pragma unroll
                for(int mt=0;mt<2;mt++){
                    int rbase = m0 + mt*16;
                    af[mt][0] = Au[(rbase+g  )*HST + s*8 + t    ];
                    af[mt][1] = Au[(rbase+8+g)*HST + s*8 + t    ];
                    af[mt][2] = Au[(rbase+g  )*HST + s*8 + t + 4];
                    af[mt][3] = Au[(rbase+8+g)*HST + s*8 + t + 4];
                }
                uint32_t bf[8][2];
                #pragma unroll
                for(int nt=0;nt<8;nt++){
                    bf[nt][0] = Bu[(n0+nt*8+g)*HST + s*8 + t    ];
                    bf[nt][1] = Bu[(n0+nt*8+g)*HST + s*8 + t + 4];
                }
                #pragma unroll
                for(int mt=0;mt<2;mt++)
                    #pragma unroll
                    for(int nt=0;nt<8;nt++)
                        mma16(acc[mt][nt], af[mt], bf[nt]);
            }
        }

        if(kt+1 < NT){
            uint32_t* An = As[(kt+1)&1];
            uint32_t* Bn = Bs[(kt+1)&1];
            #pragma unroll
            for(int r=0;r<4;r++){
                int row = alr + r*32;
                An[row*HST + aq*2    ] = h2u(ar[r].x, ar[r].y);
                An[row*HST + aq*2 + 1] = h2u(ar[r].z, ar[r].w);
                Bn[row*HST + aq*2    ] = h2u(br[r].x, br[r].y);
                Bn[row*HST + aq*2 + 1] = h2u(br[r].z, br[r].w);
            }
        }
        __syncthreads();
    }

    // epilogue
    #pragma unroll
    for(int mt=0;mt<2;mt++){
        int r0 = bm*128 + m0 + mt*16 + g;
        int r1 = r0 + 8;
        #pragma unroll
        for(int nt=0;nt<8;nt++){
            int col = bn*128 + n0 + nt*8 + t*2;
            if(col < N){
                float v0 = acc[mt][nt][0], v1 = acc[mt][nt][1];
                float v2 = acc[mt][nt][2], v3 = acc[mt][nt][3];
                if(bias){ float b0=bias[col], b1=bias[col+1]; v0+=b0; v1+=b1; v2+=b0; v3+=b1; }
                if(dogelu){ v0=gelu_f(v0); v1=gelu_f(v1); v2=gelu_f(v2); v3=gelu_f(v3); }
                long i0 = (long)r0*N + col, i1 = (long)r1*N + col;
                if(Rb){ v0+=Rb[i0]; v1+=Rb[i0+1]; v2+=Rb[i1]; v3+=Rb[i1+1]; }
                Cb[i0]=v0; Cb[i0+1]=v1; Cb[i1]=v2; Cb[i1+1]=v3;
            }
        }
    }
}

// ---------------- LayerNorm ----------------
__global__ void ln_kernel(const float* __restrict__ x, const float* __restrict__ g,
                          const float* __restrict__ b, float* __restrict__ y, int N)
{
    __shared__ float sh[32];
    long base = (long)blockIdx.x * N;
    float s=0.f, ss=0.f;
    for(int c=threadIdx.x;c<N;c+=blockDim.x){
        float v = x[base+c]; s += v; ss += v*v;
    }
    s  = blockReduceSum(s,  sh);
    ss = blockReduceSum(ss, sh);
    float mu  = s  / (float)N;
    float var = ss / (float)N - mu*mu;
    float rs  = rsqrtf(var + 1e-6f);
    for(int c=threadIdx.x;c<N;c+=blockDim.x){
        y[base+c] = (x[base+c]-mu)*rs*g[c] + b[c];
    }
}

// ---------------- softmax over rows of 1024 ----------------
__global__ void softmax1024(float* __restrict__ S)
{
    __shared__ float sh[32];
    long base = (long)blockIdx.x * 1024;
    int tid = threadIdx.x;
    float v0=S[base+tid], v1=S[base+tid+256], v2=S[base+tid+512], v3=S[base+tid+768];
    float m = fmaxf(fmaxf(v0,v1), fmaxf(v2,v3));
    float M = blockReduceMax(m, sh);
    v0=__expf(v0-M); v1=__expf(v1-M); v2=__expf(v2-M); v3=__expf(v3-M);
    float T = blockReduceSum(v0+v1+v2+v3, sh);
    float inv = 1.f / T;
    S[base+tid]     = v0*inv;
    S[base+tid+256] = v1*inv;
    S[base+tid+512] = v2*inv;
    S[base+tid+768] = v3*inv;
}

// ---------------- RoPE tables ----------------
__global__ void init_rope()
{
    int gid = blockIdx.x*blockDim.x + threadIdx.x;
    if(gid >= IMG_TOK*HD) return;
    int d = gid % HD, tt = gid / HD;
    int iw=tt&1, ih=(tt>>1)&1, bw=(tt>>2)&15, bh=tt>>6;
    int gh = bh*2+ih, gw = bw*2+iw;
    int dd = d % 36;
    int pos, i;
    if(dd < 18){ i = dd;      pos = gh; }
    else       { i = dd - 18; pos = gw; }
    float inv = powf(10000.0f, -((float)(2*i)/36.0f));
    float ang = (float)pos * inv;
    g_cos[gid] = cosf(ang);
    g_sin[gid] = sinf(ang);
}

// ---------------- pos-embed bilinear add ----------------
__global__ void add_pos(float* __restrict__ x, const float* __restrict__ pe)
{
    int gid = blockIdx.x*blockDim.x + threadIdx.x;
    if(gid >= SEQ*HIDDEN) return;
    int j = gid % HIDDEN; int s = gid / HIDDEN;
    int tt = s & 1023;
    int iw=tt&1, ih=(tt>>1)&1, bw=(tt>>2)&15, bh=tt>>6;
    int gh = bh*2+ih, gw = bw*2+iw;
    double hl = (double)gh*47.0/31.0;
    double wl = (double)gw*47.0/31.0;
    int h0=(int)hl; int h1=min(h0+1,47); float dh=(float)(hl-(double)h0);
    int w0=(int)wl; int w1=min(w0+1,47); float dw=(float)(wl-(double)w0);
    float p00 = pe[(h0*48+w0)*HIDDEN + j];
    float p01 = pe[(h0*48+w1)*HIDDEN + j];
    float p10 = pe[(h1*48+w0)*HIDDEN + j];
    float p11 = pe[(h1*48+w1)*HIDDEN + j];
    float v = (1.f-dh)*((1.f-dw)*p00 + dw*p01) + dh*((1.f-dw)*p10 + dw*p11);
    x[gid] += v;
}

// ---------------- RoPE apply + repack (V stored transposed) ----------------
__global__ void rope_pack(const float* __restrict__ qkv, float* __restrict__ q2,
                          float* __restrict__ k2, float* __restrict__ v2t)
{
    int gid = blockIdx.x*blockDim.x + threadIdx.x;
    if(gid >= SEQ*HEADS*HD) return;
    int d = gid % HD;
    int h = (gid / HD) % HEADS;
    int s = gid / (HD*HEADS);
    int tt = s & (IMG_TOK-1);
    int b = s >> 10;
    float c  = g_cos[tt*HD + d];
    float sn = g_sin[tt*HD + d];
    long base = (long)s*(3*HIDDEN) + h*HD;
    float qd = qkv[base + d];
    float kd = qkv[base + HIDDEN + d];
    int   dp  = (d<36) ? d+36 : d-36;
    float sgn = (d<36) ? -1.f : 1.f;
    float qp = qkv[base + dp];
    float kp = qkv[base + HIDDEN + dp];
    long oi = ((long)(b*HEADS + h)*IMG_TOK + tt)*HD + d;
    q2[oi] = (qd*c + sgn*qp*sn) * SCALE_Q;
    k2[oi] =  kd*c + sgn*kp*sn;
    v2t[((long)(b*HEADS + h)*HD + d)*IMG_TOK + tt] = qkv[base + 2*HIDDEN + d];
}

// ---------------- attention out repack ----------------
__global__ void unpack_attn(const float* __restrict__ o2, float* __restrict__ attn)
{
    int gid = blockIdx.x*blockDim.x + threadIdx.x;
    if(gid >= SEQ*HEADS*HD) return;
    int d = gid % HD;
    int h = (gid / HD) % HEADS;
    int s = gid / (HD*HEADS);
    int tt = s & (IMG_TOK-1);
    int b = s >> 10;
    attn[(long)s*HIDDEN + h*HD + d] =
        o2[((long)(b*HEADS + h)*IMG_TOK + tt)*HD + d];
}

// ---------------- host-side launch helper ----------------
static inline void gemmh(const float*A,const float*B,float*C,const float*bias,const float*res,
                         int M,int N,int K,int batch,long sA,long sB,long sC,int dogelu){
    dim3 g((N+127)/128, M/128, batch);
    gemm_h<<<g,256>>>(A,B,C,bias,res,M,N,K,sA,sB,sC,dogelu);
}

extern "C" void kernel_launch(void* const* d_in, const int* in_sizes, int n_in,
                              void* d_out, int out_size)
{
    const float* pixel   = (const float*)d_in[0];
    const float* patch_w = (const float*)d_in[1];
    const float* patch_b = (const float*)d_in[2];
    const float* pos_e   = (const float*)d_in[3];
    const float* qkv_w   = (const float*)d_in[4];
    const float* qkv_b   = (const float*)d_in[5];
    const float* proj_w  = (const float*)d_in[6];
    const float* proj_b  = (const float*)d_in[7];
    const float* ln1_g   = (const float*)d_in[8];
    const float* ln1_b   = (const float*)d_in[9];
    const float* ln2_g   = (const float*)d_in[10];
    const float* ln2_b   = (const float*)d_in[11];
    const float* fc1_w   = (const float*)d_in[12];
    const float* fc1_b   = (const float*)d_in[13];
    const float* fc2_w   = (const float*)d_in[14];
    const float* fc2_b   = (const float*)d_in[15];
    const float* m_ln_g  = (const float*)d_in[16];
    const float* m_ln_b  = (const float*)d_in[17];
    const float* m_fc1_w = (const float*)d_in[18];
    const float* m_fc1_b = (const float*)d_in[19];
    const float* m_fc2_w = (const float*)d_in[20];
    const float* m_fc2_b = (const float*)d_in[21];
    const float* ds_ln_g = (const float*)d_in[22];
    const float* ds_ln_b = (const float*)d_in[23];
    const float* ds_fc1_w= (const float*)d_in[24];
    const float* ds_fc1_b= (const float*)d_in[25];
    const float* ds_fc2_w= (const float*)d_in[26];
    const float* ds_fc2_b= (const float*)d_in[27];
    float* out = (float*)d_out;

    float *px,*pxn,*pqkv,*pq2,*pk2,*pv2t,*psc,*po2,*pattn,*ph,*pmh,*pmf;
    cudaGetSymbolAddress((void**)&px,   g_x);
    cudaGetSymbolAddress((void**)&pxn,  g_xn);
    cudaGetSymbolAddress((void**)&pqkv, g_qkv);
    cudaGetSymbolAddress((void**)&pq2,  g_q2);
    cudaGetSymbolAddress((void**)&pk2,  g_k2);
    cudaGetSymbolAddress((void**)&pv2t, g_v2t);
    cudaGetSymbolAddress((void**)&psc,  g_sc);
    cudaGetSymbolAddress((void**)&po2,  g_o2);
    cudaGetSymbolAddress((void**)&pattn,g_attn);
    cudaGetSymbolAddress((void**)&ph,   g_h);
    cudaGetSymbolAddress((void**)&pmh,  g_mh);
    cudaGetSymbolAddress((void**)&pmf,  g_mf);

    const int EW = 256;
    init_rope<<<(IMG_TOK*HD + EW-1)/EW, EW>>>();

    gemmh(pixel, patch_w, px, patch_b, nullptr, SEQ, HIDDEN, PATCHD, 1, 0,0,0, 0);
    add_pos<<<(SEQ*HIDDEN + EW-1)/EW, EW>>>(px, pos_e);

    const int NQH = SEQ*HEADS*HD;
    for(int i=0;i<DEPTH;i++){
        ln_kernel<<<SEQ,256>>>(px, ln1_g+(long)i*HIDDEN, ln1_b+(long)i*HIDDEN, pxn, HIDDEN);
        gemmh(pxn, qkv_w+(long)i*3*HIDDEN*HIDDEN, pqkv, qkv_b+(long)i*3*HIDDEN, nullptr,
              SEQ, 3*HIDDEN, HIDDEN, 1, 0,0,0, 0);
        rope_pack<<<(NQH + EW-1)/EW, EW>>>(pqkv, pq2, pk2, pv2t);
        // S = Q @ K^T
        gemmh(pq2, pk2, psc, nullptr, nullptr,
              IMG_TOK, IMG_TOK, HD, NBH,
              (long)IMG_TOK*HD, (long)IMG_TOK*HD, (long)IMG_TOK*IMG_TOK, 0);
        softmax1024<<<NBH*IMG_TOK, 256>>>(psc);
        // O = P @ V  (V pre-transposed -> BT form, K=1024)
        gemmh(psc, pv2t, po2, nullptr, nullptr,
              IMG_TOK, HD, IMG_TOK, NBH,
              (long)IMG_TOK*IMG_TOK, (long)HD*IMG_TOK, (long)IMG_TOK*HD, 0);
        unpack_attn<<<(NQH + EW-1)/EW, EW>>>(po2, pattn);
        gemmh(pattn, proj_w+(long)i*HIDDEN*HIDDEN, px, proj_b+(long)i*HIDDEN, px,
              SEQ, HIDDEN, HIDDEN, 1, 0,0,0, 0);

        ln_kernel<<<SEQ,256>>>(px, ln2_g+(long)i*HIDDEN, ln2_b+(long)i*HIDDEN, pxn, HIDDEN);
        gemmh(pxn, fc1_w+(long)i*INTER*HIDDEN, ph, fc1_b+(long)i*INTER, nullptr,
              SEQ, INTER, HIDDEN, 1, 0,0,0, 1);
        gemmh(ph, fc2_w+(long)i*HIDDEN*INTER, px, fc2_b+(long)i*HIDDEN, px,
              SEQ, HIDDEN, INTER, 1, 0,0,0, 0);

        if(i==2 || i==4){
            int j = (i==2) ? 0 : 1;
            ln_kernel<<<1024,256>>>(px, ds_ln_g+(long)j*MERGED, ds_ln_b+(long)j*MERGED, pmh, MERGED);
            gemmh(pmh, ds_fc1_w+(long)j*MERGED*MERGED, pmf, ds_fc1_b+(long)j*MERGED, nullptr,
                  1024, MERGED, MERGED, 1, 0,0,0, 1);
            gemmh(pmf, ds_fc2_w+(long)j*OUTH*MERGED, out+(long)(1+j)*1024*OUTH,
                  ds_fc2_b+(long)j*OUTH, nullptr,
                  1024, OUTH, MERGED, 1, 0,0,0, 0);
        }
    }

    ln_kernel<<<SEQ,256>>>(px, m_ln_g, m_ln_b, pmh, HIDDEN);
    gemmh(pmh, m_fc1_w, pmf, m_fc1_b, nullptr, 1024, MERGED, MERGED, 1, 0,0,0, 1);
    gemmh(pmf, m_fc2_w, out, m_fc2_b, nullptr, 1024, OUTH, MERGED, 1, 0,0,0, 0);
}

// round 5
// speedup vs baseline: 4.6753x; 1.1491x over previous
#include <cuda_runtime.h>
#include <cuda_fp16.h>
#include <math.h>
#include <stdint.h>

// ---------------- problem constants ----------------
#define SEQ      4096
#define HIDDEN   1152
#define HEADS    16
#define HD       72
#define INTER    4304
#define DEPTH    6
#define MERGED   4608
#define OUTH     2048
#define PATCHD   1536
#define IMG_TOK  1024
#define NBH      64
#define SCALE_Q  0.11785113019775793f

// ---------------- device scratch ----------------
__device__ float g_x   [SEQ*HIDDEN];
__device__ float g_xn  [SEQ*HIDDEN];
__device__ float g_qkv [SEQ*3*HIDDEN];
__device__ float g_q2  [NBH*IMG_TOK*HD];
__device__ float g_k2  [NBH*IMG_TOK*HD];
__device__ float g_v2t [NBH*HD*IMG_TOK];     // V transposed: [bh][d][t]
__device__ float g_attn[SEQ*HIDDEN];
__device__ float g_h   [SEQ*INTER];
__device__ float g_mh  [SEQ*HIDDEN];
__device__ float g_mf  [1024*MERGED];
__device__ float g_cos [IMG_TOK*HD];
__device__ float g_sin [IMG_TOK*HD];

// ---------------- helpers ----------------
__device__ __forceinline__ float gelu_f(float x){
    float x3 = x*x*x;
    return 0.5f*x*(1.0f + tanhf(0.7978845608028654f*(x + 0.044715f*x3)));
}

__device__ __forceinline__ uint32_t h2u(float a, float b){
    __half2 h = __floats2half2_rn(a, b);
    return *(uint32_t*)&h;
}

__device__ __forceinline__ void mma16(float* c, const uint32_t* a, const uint32_t* b){
    asm volatile("mma.sync.aligned.m16n8k16.row.col.f32.f16.f16.f32 "
        "{%0,%1,%2,%3},{%4,%5,%6,%7},{%8,%9},{%0,%1,%2,%3};"
        : "+f"(c[0]),"+f"(c[1]),"+f"(c[2]),"+f"(c[3])
        : "r"(a[0]),"r"(a[1]),"r"(a[2]),"r"(a[3]),"r"(b[0]),"r"(b[1]));
}

__device__ __forceinline__ float blockReduceSum(float v, float* sh){
    int tid = threadIdx.x;
    __syncthreads();
    #pragma unroll
    for(int o=16;o>0;o>>=1) v += __shfl_xor_sync(0xffffffffu, v, o);
    if((tid&31)==0) sh[tid>>5] = v;
    __syncthreads();
    if(tid < 32){
        float r = (tid < (int)(blockDim.x>>5)) ? sh[tid] : 0.f;
        #pragma unroll
        for(int o=16;o>0;o>>=1) r += __shfl_xor_sync(0xffffffffu, r, o);
        if(tid==0) sh[0] = r;
    }
    __syncthreads();
    return sh[0];
}

// ---------------- FP16 tensor-core GEMM (BT form) ----------------
#define HST 20

__global__ __launch_bounds__(256)
void gemm_h(const float* __restrict__ A, const float* __restrict__ B,
            float* __restrict__ C, const float* __restrict__ bias,
            const float* __restrict__ res,
            int M, int N, int K,
            long sA, long sB, long sC, int dogelu)
{
    __shared__ uint32_t As[2][128*HST];
    __shared__ uint32_t Bs[2][128*HST];

    const int tid  = threadIdx.x;
    const int lane = tid & 31, warp = tid >> 5;
    const int g = lane >> 2, t = lane & 3;
    const int wm = warp >> 1, wn = warp & 1;
    const int m0 = wm*32, n0 = wn*64;

    const int bn = blockIdx.x, bm = blockIdx.y, bz = blockIdx.z;
    const float* Ab = A + (long)bz*sA;
    const float* Bb = B + (long)bz*sB;
    float*       Cb = C + (long)bz*sC;
    const float* Rb = res ? (res + (long)bz*sC) : (const float*)0;

    float acc[2][8][4];
    #pragma unroll
    for(int i=0;i<2;i++)
        #pragma unroll
        for(int j=0;j<8;j++)
            #pragma unroll
            for(int q=0;q<4;q++) acc[i][j][q]=0.f;

    const int alr = tid >> 3;
    const int aq  = tid & 7;
    const int alk = aq * 4;

    const int NT = (K+31)/32;
    float4 ar[4], br[4];

    {
        #pragma unroll
        for(int r=0;r<4;r++){
            int row = alr + r*32, k = alk;
            ar[r] = (k<K) ? *(const float4*)(Ab + (long)(bm*128+row)*K + k)
                          : make_float4(0,0,0,0);
            int brow = bn*128 + row;
            br[r] = (brow<N && k<K) ? *(const float4*)(Bb + (long)brow*K + k)
                                    : make_float4(0,0,0,0);
        }
        #pragma unroll
        for(int r=0;r<4;r++){
            int row = alr + r*32;
            As[0][row*HST + aq*2    ] = h2u(ar[r].x, ar[r].y);
            As[0][row*HST + aq*2 + 1] = h2u(ar[r].z, ar[r].w);
            Bs[0][row*HST + aq*2    ] = h2u(br[r].x, br[r].y);
            Bs[0][row*HST + aq*2 + 1] = h2u(br[r].z, br[r].w);
        }
    }
    __syncthreads();

    for(int kt=0; kt<NT; kt++){
        if(kt+1 < NT){
            int k0 = (kt+1)*32;
            #pragma unroll
            for(int r=0;r<4;r++){
                int row = alr + r*32, k = k0 + alk;
                ar[r] = (k<K) ? *(const float4*)(Ab + (long)(bm*128+row)*K + k)
                              : make_float4(0,0,0,0);
                int brow = bn*128 + row;
                br[r] = (brow<N && k<K) ? *(const float4*)(Bb + (long)brow*K + k)
                                        : make_float4(0,0,0,0);
            }
        }

        {
            const uint32_t* Au = As[kt&1];
            const uint32_t* Bu = Bs[kt&1];
            #pragma unroll
            for(int s=0;s<2;s++){
                uint32_t af[2][4];
                #pragma unroll
                for(int mt=0;mt<2;mt++){
                    int rbase = m0 + mt*16;
                    af[mt][0] = Au[(rbase+g  )*HST + s*8 + t    ];
                    af[mt][1] = Au[(rbase+8+g)*HST + s*8 + t    ];
                    af[mt][2] = Au[(rbase+g  )*HST + s*8 + t + 4];
                    af[mt][3] = Au[(rbase+8+g)*HST + s*8 + t + 4];
                }
                uint32_t bf[8][2];
                #pragma unroll
                for(int nt=0;nt<8;nt++){
                    bf[nt][0] = Bu[(n0+nt*8+g)*HST + s*8 + t    ];
                    bf[nt][1] = Bu[(n0+nt*8+g)*HST + s*8 + t + 4];
                }
                #pragma unroll
                for(int mt=0;mt<2;mt++)
                    #pragma unroll
                    for(int nt=0;nt<8;nt++)
                        mma16(acc[mt][nt], af[mt], bf[nt]);
            }
        }

        if(kt+1 < NT){
            uint32_t* An = As[(kt+1)&1];
            uint32_t* Bn = Bs[(kt+1)&1];
            #pragma unroll
            for(int r=0;r<4;r++){
                int row = alr + r*32;
                An[row*HST + aq*2    ] = h2u(ar[r].x, ar[r].y);
                An[row*HST + aq*2 + 1] = h2u(ar[r].z, ar[r].w);
                Bn[row*HST + aq*2    ] = h2u(br[r].x, br[r].y);
                Bn[row*HST + aq*2 + 1] = h2u(br[r].z, br[r].w);
            }
        }
        __syncthreads();
    }

    #pragma unroll
    for(int mt=0;mt<2;mt++){
        int r0 = bm*128 + m0 + mt*16 + g;
        int r1 = r0 + 8;
        #pragma unroll
        for(int nt=0;nt<8;nt++){
            int col = bn*128 + n0 + nt*8 + t*2;
            if(col < N){
                float v0 = acc[mt][nt][0], v1 = acc[mt][nt][1];
                float v2 = acc[mt][nt][2], v3 = acc[mt][nt][3];
                if(bias){ float b0=bias[col], b1=bias[col+1]; v0+=b0; v1+=b1; v2+=b0; v3+=b1; }
                if(dogelu){ v0=gelu_f(v0); v1=gelu_f(v1); v2=gelu_f(v2); v3=gelu_f(v3); }
                long i0 = (long)r0*N + col, i1 = (long)r1*N + col;
                if(Rb){ v0+=Rb[i0]; v1+=Rb[i0+1]; v2+=Rb[i1]; v3+=Rb[i1+1]; }
                Cb[i0]=v0; Cb[i0+1]=v1; Cb[i1]=v2; Cb[i1+1]=v3;
            }
        }
    }
}

// ---------------- fused flash attention ----------------
// grid (8, 64): x = q-block of 128 tokens, y = (image,head).
// 256 threads = 8 warps; warp w owns q rows [w*16, w*16+16).
// K-blocks of 64 tokens, 16 iterations. Output written directly to attn layout.
#define QST 44   // Q/K smem row stride in uint32 (40 half2 used + 4 pad)
#define VST 36   // V^T smem row stride (32 half2 used + 4 pad)

__global__ __launch_bounds__(256)
void flash_attn(const float* __restrict__ q2, const float* __restrict__ k2,
                const float* __restrict__ v2t, float* __restrict__ attn)
{
    __shared__ uint32_t Qs[128*QST];
    __shared__ uint32_t Ks[64*QST];
    __shared__ uint32_t Vs[72*VST];

    const int tid = threadIdx.x;
    const int lane = tid & 31, w = tid >> 5;
    const int g = lane >> 2, tq = lane & 3;
    const int qb = blockIdx.x, bh = blockIdx.y;

    // ---- load Q block (128 x 72 f32 -> fp16, zero-pad cols 72..79) ----
    const float* Qg = q2 + ((long)bh*IMG_TOK + qb*128)*HD;
    for(int idx = tid; idx < 128*40; idx += 256){
        int r = idx/40, c = idx%40;
        float a = (2*c   < HD) ? Qg[(long)r*HD + 2*c  ] : 0.f;
        float b = (2*c+1 < HD) ? Qg[(long)r*HD + 2*c+1] : 0.f;
        Qs[r*QST + c] = h2u(a, b);
    }
    __syncthreads();

    // preload Q fragments (5 k-steps of 16 over padded HD=80)
    uint32_t qf[5][4];
    #pragma unroll
    for(int s=0;s<5;s++){
        qf[s][0] = Qs[(w*16+g  )*QST + s*8 + tq    ];
        qf[s][1] = Qs[(w*16+8+g)*QST + s*8 + tq    ];
        qf[s][2] = Qs[(w*16+g  )*QST + s*8 + tq + 4];
        qf[s][3] = Qs[(w*16+8+g)*QST + s*8 + tq + 4];
    }

    float m0 = -3.4e38f, m1 = -3.4e38f, l0 = 0.f, l1 = 0.f;
    float o[9][4];
    #pragma unroll
    for(int nt=0;nt<9;nt++){ o[nt][0]=0.f; o[nt][1]=0.f; o[nt][2]=0.f; o[nt][3]=0.f; }

    const float* Kg0 = k2  + (long)bh*IMG_TOK*HD;
    const float* Vg0 = v2t + (long)bh*HD*IMG_TOK;

    for(int kb=0; kb<16; kb++){
        __syncthreads();   // previous iteration's smem reads done
        // load K block (64 x 72 -> fp16, pad to 80)
        const float* Kg = Kg0 + (long)kb*64*HD;
        for(int idx = tid; idx < 64*40; idx += 256){
            int r = idx/40, c = idx%40;
            float a = (2*c   < HD) ? Kg[(long)r*HD + 2*c  ] : 0.f;
            float b = (2*c+1 < HD) ? Kg[(long)r*HD + 2*c+1] : 0.f;
            Ks[r*QST + c] = h2u(a, b);
        }
        // load V^T block (72 rows x 64 tokens)
        const float* Vg = Vg0 + kb*64;
        for(int idx = tid; idx < 72*32; idx += 256){
            int r = idx/32, c = idx%32;
            Vs[r*VST + c] = h2u(Vg[(long)r*IMG_TOK + 2*c], Vg[(long)r*IMG_TOK + 2*c+1]);
        }
        __syncthreads();

        // ---- S = Q @ K^T (16 x 64 per warp) ----
        float sacc[8][4];
        #pragma unroll
        for(int nt=0;nt<8;nt++){ sacc[nt][0]=0.f; sacc[nt][1]=0.f; sacc[nt][2]=0.f; sacc[nt][3]=0.f; }
        #pragma unroll
        for(int s=0;s<5;s++){
            #pragma unroll
            for(int nt=0;nt<8;nt++){
                uint32_t bf[2];
                bf[0] = Ks[(nt*8+g)*QST + s*8 + tq    ];
                bf[1] = Ks[(nt*8+g)*QST + s*8 + tq + 4];
                mma16(sacc[nt], qf[s], bf);
            }
        }

        // ---- online softmax ----
        float rm0 = -3.4e38f, rm1 = -3.4e38f;
        #pragma unroll
        for(int nt=0;nt<8;nt++){
            rm0 = fmaxf(rm0, fmaxf(sacc[nt][0], sacc[nt][1]));
            rm1 = fmaxf(rm1, fmaxf(sacc[nt][2], sacc[nt][3]));
        }
        rm0 = fmaxf(rm0, __shfl_xor_sync(0xffffffffu, rm0, 1));
        rm0 = fmaxf(rm0, __shfl_xor_sync(0xffffffffu, rm0, 2));
        rm1 = fmaxf(rm1, __shfl_xor_sync(0xffffffffu, rm1, 1));
        rm1 = fmaxf(rm1, __shfl_xor_sync(0xffffffffu, rm1, 2));

        float m0n = fmaxf(m0, rm0), m1n = fmaxf(m1, rm1);
        float a0 = __expf(m0 - m0n), a1 = __expf(m1 - m1n);
        m0 = m0n; m1 = m1n;

        float rs0 = 0.f, rs1 = 0.f;
        #pragma unroll
        for(int nt=0;nt<8;nt++){
            sacc[nt][0] = __expf(sacc[nt][0] - m0n);
            sacc[nt][1] = __expf(sacc[nt][1] - m0n);
            sacc[nt][2] = __expf(sacc[nt][2] - m1n);
            sacc[nt][3] = __expf(sacc[nt][3] - m1n);
            rs0 += sacc[nt][0] + sacc[nt][1];
            rs1 += sacc[nt][2] + sacc[nt][3];
        }
        rs0 += __shfl_xor_sync(0xffffffffu, rs0, 1);
        rs0 += __shfl_xor_sync(0xffffffffu, rs0, 2);
        rs1 += __shfl_xor_sync(0xffffffffu, rs1, 1);
        rs1 += __shfl_xor_sync(0xffffffffu, rs1, 2);
        l0 = l0*a0 + rs0;
        l1 = l1*a1 + rs1;

        #pragma unroll
        for(int nt=0;nt<9;nt++){
            o[nt][0]*=a0; o[nt][1]*=a0; o[nt][2]*=a1; o[nt][3]*=a1;
        }

        // ---- O += P @ V : P fragments come straight from sacc ----
        #pragma unroll
        for(int ks=0;ks<4;ks++){
            uint32_t pf[4];
            pf[0] = h2u(sacc[2*ks  ][0], sacc[2*ks  ][1]);
            pf[1] = h2u(sacc[2*ks  ][2], sacc[2*ks  ][3]);
            pf[2] = h2u(sacc[2*ks+1][0], sacc[2*ks+1][1]);
            pf[3] = h2u(sacc[2*ks+1][2], sacc[2*ks+1][3]);
            #pragma unroll
            for(int nt=0;nt<9;nt++){
                uint32_t bf[2];
                bf[0] = Vs[(nt*8+g)*VST + ks*8 + tq    ];
                bf[1] = Vs[(nt*8+g)*VST + ks*8 + tq + 4];
                mma16(o[nt], pf, bf);
            }
        }
    }

    // ---- epilogue: normalize and write directly into attn layout ----
    float inv0 = 1.f/l0, inv1 = 1.f/l1;
    int b = bh >> 4, h = bh & 15;
    int t0 = qb*128 + w*16 + g;
    long base0 = (long)(b*IMG_TOK + t0    )*HIDDEN + h*HD;
    long base1 = (long)(b*IMG_TOK + t0 + 8)*HIDDEN + h*HD;
    #pragma unroll
    for(int nt=0;nt<9;nt++){
        int col = nt*8 + tq*2;
        attn[base0 + col    ] = o[nt][0]*inv0;
        attn[base0 + col + 1] = o[nt][1]*inv0;
        attn[base1 + col    ] = o[nt][2]*inv1;
        attn[base1 + col + 1] = o[nt][3]*inv1;
    }
}

// ---------------- LayerNorm ----------------
__global__ void ln_kernel(const float* __restrict__ x, const float* __restrict__ g,
                          const float* __restrict__ b, float* __restrict__ y, int N)
{
    __shared__ float sh[32];
    long base = (long)blockIdx.x * N;
    float s=0.f, ss=0.f;
    for(int c=threadIdx.x;c<N;c+=blockDim.x){
        float v = x[base+c]; s += v; ss += v*v;
    }
    s  = blockReduceSum(s,  sh);
    ss = blockReduceSum(ss, sh);
    float mu  = s  / (float)N;
    float var = ss / (float)N - mu*mu;
    float rs  = rsqrtf(var + 1e-6f);
    for(int c=threadIdx.x;c<N;c+=blockDim.x){
        y[base+c] = (x[base+c]-mu)*rs*g[c] + b[c];
    }
}

// ---------------- RoPE tables ----------------
__global__ void init_rope()
{
    int gid = blockIdx.x*blockDim.x + threadIdx.x;
    if(gid >= IMG_TOK*HD) return;
    int d = gid % HD, tt = gid / HD;
    int iw=tt&1, ih=(tt>>1)&1, bw=(tt>>2)&15, bh=tt>>6;
    int gh = bh*2+ih, gw = bw*2+iw;
    int dd = d % 36;
    int pos, i;
    if(dd < 18){ i = dd;      pos = gh; }
    else       { i = dd - 18; pos = gw; }
    float inv = powf(10000.0f, -((float)(2*i)/36.0f));
    float ang = (float)pos * inv;
    g_cos[gid] = cosf(ang);
    g_sin[gid] = sinf(ang);
}

// ---------------- pos-embed bilinear add ----------------
__global__ void add_pos(float* __restrict__ x, const float* __restrict__ pe)
{
    int gid = blockIdx.x*blockDim.x + threadIdx.x;
    if(gid >= SEQ*HIDDEN) return;
    int j = gid % HIDDEN; int s = gid / HIDDEN;
    int tt = s & 1023;
    int iw=tt&1, ih=(tt>>1)&1, bw=(tt>>2)&15, bh=tt>>6;
    int gh = bh*2+ih, gw = bw*2+iw;
    double hl = (double)gh*47.0/31.0;
    double wl = (double)gw*47.0/31.0;
    int h0=(int)hl; int h1=min(h0+1,47); float dh=(float)(hl-(double)h0);
    int w0=(int)wl; int w1=min(w0+1,47); float dw=(float)(wl-(double)w0);
    float p00 = pe[(h0*48+w0)*HIDDEN + j];
    float p01 = pe[(h0*48+w1)*HIDDEN + j];
    float p10 = pe[(h1*48+w0)*HIDDEN + j];
    float p11 = pe[(h1*48+w1)*HIDDEN + j];
    float v = (1.f-dh)*((1.f-dw)*p00 + dw*p01) + dh*((1.f-dw)*p10 + dw*p11);
    x[gid] += v;
}

// ---------------- RoPE apply + repack (V stored transposed) ----------------
__global__ void rope_pack(const float* __restrict__ qkv, float* __restrict__ q2,
                          float* __restrict__ k2, float* __restrict__ v2t)
{
    int gid = blockIdx.x*blockDim.x + threadIdx.x;
    if(gid >= SEQ*HEADS*HD) return;
    int d = gid % HD;
    int h = (gid / HD) % HEADS;
    int s = gid / (HD*HEADS);
    int tt = s & (IMG_TOK-1);
    int b = s >> 10;
    float c  = g_cos[tt*HD + d];
    float sn = g_sin[tt*HD + d];
    long base = (long)s*(3*HIDDEN) + h*HD;
    float qd = qkv[base + d];
    float kd = qkv[base + HIDDEN + d];
    int   dp  = (d<36) ? d+36 : d-36;
    float sgn = (d<36) ? -1.f : 1.f;
    float qp = qkv[base + dp];
    float kp = qkv[base + HIDDEN + dp];
    long oi = ((long)(b*HEADS + h)*IMG_TOK + tt)*HD + d;
    q2[oi] = (qd*c + sgn*qp*sn) * SCALE_Q;
    k2[oi] =  kd*c + sgn*kp*sn;
    v2t[((long)(b*HEADS + h)*HD + d)*IMG_TOK + tt] = qkv[base + 2*HIDDEN + d];
}

// ---------------- host-side launch helper ----------------
static inline void gemmh(const float*A,const float*B,float*C,const float*bias,const float*res,
                         int M,int N,int K,int batch,long sA,long sB,long sC,int dogelu){
    dim3 g((N+127)/128, M/128, batch);
    gemm_h<<<g,256>>>(A,B,C,bias,res,M,N,K,sA,sB,sC,dogelu);
}

extern "C" void kernel_launch(void* const* d_in, const int* in_sizes, int n_in,
                              void* d_out, int out_size)
{
    const float* pixel   = (const float*)d_in[0];
    const float* patch_w = (const float*)d_in[1];
    const float* patch_b = (const float*)d_in[2];
    const float* pos_e   = (const float*)d_in[3];
    const float* qkv_w   = (const float*)d_in[4];
    const float* qkv_b   = (const float*)d_in[5];
    const float* proj_w  = (const float*)d_in[6];
    const float* proj_b  = (const float*)d_in[7];
    const float* ln1_g   = (const float*)d_in[8];
    const float* ln1_b   = (const float*)d_in[9];
    const float* ln2_g   = (const float*)d_in[10];
    const float* ln2_b   = (const float*)d_in[11];
    const float* fc1_w   = (const float*)d_in[12];
    const float* fc1_b   = (const float*)d_in[13];
    const float* fc2_w   = (const float*)d_in[14];
    const float* fc2_b   = (const float*)d_in[15];
    const float* m_ln_g  = (const float*)d_in[16];
    const float* m_ln_b  = (const float*)d_in[17];
    const float* m_fc1_w = (const float*)d_in[18];
    const float* m_fc1_b = (const float*)d_in[19];
    const float* m_fc2_w = (const float*)d_in[20];
    const float* m_fc2_b = (const float*)d_in[21];
    const float* ds_ln_g = (const float*)d_in[22];
    const float* ds_ln_b = (const float*)d_in[23];
    const float* ds_fc1_w= (const float*)d_in[24];
    const float* ds_fc1_b= (const float*)d_in[25];
    const float* ds_fc2_w= (const float*)d_in[26];
    const float* ds_fc2_b= (const float*)d_in[27];
    float* out = (float*)d_out;

    float *px,*pxn,*pqkv,*pq2,*pk2,*pv2t,*pattn,*ph,*pmh,*pmf;
    cudaGetSymbolAddress((void**)&px,   g_x);
    cudaGetSymbolAddress((void**)&pxn,  g_xn);
    cudaGetSymbolAddress((void**)&pqkv, g_qkv);
    cudaGetSymbolAddress((void**)&pq2,  g_q2);
    cudaGetSymbolAddress((void**)&pk2,  g_k2);
    cudaGetSymbolAddress((void**)&pv2t, g_v2t);
    cudaGetSymbolAddress((void**)&pattn,g_attn);
    cudaGetSymbolAddress((void**)&ph,   g_h);
    cudaGetSymbolAddress((void**)&pmh,  g_mh);
    cudaGetSymbolAddress((void**)&pmf,  g_mf);

    const int EW = 256;
    init_rope<<<(IMG_TOK*HD + EW-1)/EW, EW>>>();

    gemmh(pixel, patch_w, px, patch_b, nullptr, SEQ, HIDDEN, PATCHD, 1, 0,0,0, 0);
    add_pos<<<(SEQ*HIDDEN + EW-1)/EW, EW>>>(px, pos_e);

    const int NQH = SEQ*HEADS*HD;
    for(int i=0;i<DEPTH;i++){
        ln_kernel<<<SEQ,256>>>(px, ln1_g+(long)i*HIDDEN, ln1_b+(long)i*HIDDEN, pxn, HIDDEN);
        gemmh(pxn, qkv_w+(long)i*3*HIDDEN*HIDDEN, pqkv, qkv_b+(long)i*3*HIDDEN, nullptr,
              SEQ, 3*HIDDEN, HIDDEN, 1, 0,0,0, 0);
        rope_pack<<<(NQH + EW-1)/EW, EW>>>(pqkv, pq2, pk2, pv2t);
        // fused attention: QK^T + softmax + PV + repack in one kernel
        flash_attn<<<dim3(8, NBH), 256>>>(pq2, pk2, pv2t, pattn);
        gemmh(pattn, proj_w+(long)i*HIDDEN*HIDDEN, px, proj_b+(long)i*HIDDEN, px,
              SEQ, HIDDEN, HIDDEN, 1, 0,0,0, 0);

        ln_kernel<<<SEQ,256>>>(px, ln2_g+(long)i*HIDDEN, ln2_b+(long)i*HIDDEN, pxn, HIDDEN);
        gemmh(pxn, fc1_w+(long)i*INTER*HIDDEN, ph, fc1_b+(long)i*INTER, nullptr,
              SEQ, INTER, HIDDEN, 1, 0,0,0, 1);
        gemmh(ph, fc2_w+(long)i*HIDDEN*INTER, px, fc2_b+(long)i*HIDDEN, px,
              SEQ, HIDDEN, INTER, 1, 0,0,0, 0);

        if(i==2 || i==4){
            int j = (i==2) ? 0 : 1;
            ln_kernel<<<1024,256>>>(px, ds_ln_g+(long)j*MERGED, ds_ln_b+(long)j*MERGED, pmh, MERGED);
            gemmh(pmh, ds_fc1_w+(long)j*MERGED*MERGED, pmf, ds_fc1_b+(long)j*MERGED, nullptr,
                  1024, MERGED, MERGED, 1, 0,0,0, 1);
            gemmh(pmf, ds_fc2_w+(long)j*OUTH*MERGED, out+(long)(1+j)*1024*OUTH,
                  ds_fc2_b+(long)j*OUTH, nullptr,
                  1024, OUTH, MERGED, 1, 0,0,0, 0);
        }
    }

    ln_kernel<<<SEQ,256>>>(px, m_ln_g, m_ln_b, pmh, HIDDEN);
    gemmh(pmh, m_fc1_w, pmf, m_fc1_b, nullptr, 1024, MERGED, MERGED, 1, 0,0,0, 1);
    gemmh(pmf, m_fc2_w, out, m_fc2_b, nullptr, 1024, OUTH, MERGED, 1, 0,0,0, 0);
}

// round 6
// speedup vs baseline: 5.0682x; 1.0840x over previous
#include <cuda_runtime.h>
#include <cuda_fp16.h>
#include <math.h>
#include <stdint.h>

// ---------------- problem constants ----------------
#define SEQ      4096
#define HIDDEN   1152
#define HEADS    16
#define HD       72
#define INTER    4304
#define DEPTH    6
#define MERGED   4608
#define OUTH     2048
#define PATCHD   1536
#define IMG_TOK  1024
#define NBH      64
#define SCALE_Q  0.11785113019775793f

// ---------------- device scratch ----------------
// fp16 weight mirrors (converted once per launch)
__device__ __half w16_patch[HIDDEN*PATCHD];
__device__ __half w16_qkv [DEPTH*3*HIDDEN*HIDDEN];
__device__ __half w16_proj[DEPTH*HIDDEN*HIDDEN];
__device__ __half w16_fc1 [DEPTH*INTER*HIDDEN];
__device__ __half w16_fc2 [DEPTH*HIDDEN*INTER];
__device__ __half w16_mfc1[MERGED*MERGED];
__device__ __half w16_mfc2[OUTH*MERGED];
__device__ __half w16_dfc1[2*MERGED*MERGED];
__device__ __half w16_dfc2[2*OUTH*MERGED];
__device__ __half g_px16  [SEQ*PATCHD];
// fp16 activations
__device__ __half g_xn16  [SEQ*HIDDEN];
__device__ __half g_q16   [NBH*IMG_TOK*HD];
__device__ __half g_k16   [NBH*IMG_TOK*HD];
__device__ __half g_v16t  [NBH*HD*IMG_TOK];
__device__ __half g_at16  [SEQ*HIDDEN];
__device__ __half g_h16   [SEQ*INTER];
__device__ __half g_mh16  [SEQ*HIDDEN];
__device__ __half g_mf16  [1024*MERGED];
// fp32 state
__device__ float g_x   [SEQ*HIDDEN];
__device__ float g_qkv [SEQ*3*HIDDEN];
__device__ float g_cos [IMG_TOK*HD];
__device__ float g_sin [IMG_TOK*HD];

// ---------------- helpers ----------------
__device__ __forceinline__ float gelu_f(float x){
    float x3 = x*x*x;
    return 0.5f*x*(1.0f + tanhf(0.7978845608028654f*(x + 0.044715f*x3)));
}
__device__ __forceinline__ uint32_t h2u(float a, float b){
    __half2 h = __floats2half2_rn(a, b);
    return *(uint32_t*)&h;
}
__device__ __forceinline__ void mma16(float* c, const uint32_t* a, const uint32_t* b){
    asm volatile("mma.sync.aligned.m16n8k16.row.col.f32.f16.f16.f32 "
        "{%0,%1,%2,%3},{%4,%5,%6,%7},{%8,%9},{%0,%1,%2,%3};"
        : "+f"(c[0]),"+f"(c[1]),"+f"(c[2]),"+f"(c[3])
        : "r"(a[0]),"r"(a[1]),"r"(a[2]),"r"(a[3]),"r"(b[0]),"r"(b[1]));
}
#define LDSM4(r, addr) \
    asm volatile("ldmatrix.sync.aligned.m8n8.x4.shared.b16 {%0,%1,%2,%3}, [%4];" \
        : "=r"((r)[0]),"=r"((r)[1]),"=r"((r)[2]),"=r"((r)[3]) : "r"(addr))
__device__ __forceinline__ void cp16(void* dst, const void* src, int nbytes){
    asm volatile("cp.async.cg.shared.global [%0], [%1], 16, %2;"
        :: "r"((uint32_t)__cvta_generic_to_shared(dst)), "l"(src), "r"(nbytes) : "memory");
}
#define CP_COMMIT() asm volatile("cp.async.commit_group;" ::: "memory")
#define CP_WAIT1()  asm volatile("cp.async.wait_group 1;" ::: "memory")
#define CP_WAIT0()  asm volatile("cp.async.wait_group 0;" ::: "memory")

__device__ __forceinline__ float blockReduceSum(float v, float* sh){
    int tid = threadIdx.x;
    __syncthreads();
    #pragma unroll
    for(int o=16;o>0;o>>=1) v += __shfl_xor_sync(0xffffffffu, v, o);
    if((tid&31)==0) sh[tid>>5] = v;
    __syncthreads();
    if(tid < 32){
        float r = (tid < (int)(blockDim.x>>5)) ? sh[tid] : 0.f;
        #pragma unroll
        for(int o=16;o>0;o>>=1) r += __shfl_xor_sync(0xffffffffu, r, o);
        if(tid==0) sh[0] = r;
    }
    __syncthreads();
    return sh[0];
}

// ---------------- fp32 -> fp16 convert ----------------
__global__ void f2h(const float* __restrict__ s, __half* __restrict__ d, long n){
    long i = (long)blockIdx.x*blockDim.x + threadIdx.x;
    long stride = (long)gridDim.x*blockDim.x;
    for(; i<n; i+=stride) d[i] = __float2half(s[i]);
}

// ---------------- fp16 GEMM: cp.async + ldmatrix ----------------
// C[M,N] = A[M,K] @ B[N,K]^T (+bias)(+gelu)(+res).  A,B fp16; C fp32 or fp16.
// Block 128x128, K-tile 32, double-buffered cp.async, 8 warps of 32x64.
#define GST 40   // smem row stride in halfs (80B; conflict-free for ldmatrix)

__global__ __launch_bounds__(256)
void gemm_a(const __half* __restrict__ A, const __half* __restrict__ B,
            void* __restrict__ Cv, const float* __restrict__ bias,
            const float* __restrict__ res,
            int M, int N, int K, int flags)   // flags: 1=gelu, 2=out fp16
{
    __shared__ __half As[2][128*GST];
    __shared__ __half Bs[2][128*GST];

    const int tid  = threadIdx.x;
    const int lane = tid & 31, warp = tid >> 5;
    const int g = lane >> 2, tq = lane & 3;
    const int wm = warp >> 1, wn = warp & 1;
    const int m0 = wm*32, n0 = wn*64;
    const int bn = blockIdx.x, bm = blockIdx.y;

    float acc[2][8][4];
    #pragma unroll
    for(int i=0;i<2;i++)
        #pragma unroll
        for(int j=0;j<8;j++)
            #pragma unroll
            for(int q=0;q<4;q++) acc[i][j][q]=0.f;

    const int NT = (K+31)/32;
    const int lr = tid >> 2;      // 0..63 (+64)
    const int seg = tid & 3;      // 16B segment in 64B k-row

    // ---- stage loader ----
    auto loadStage = [&](int buf, int k0){
        #pragma unroll
        for(int i=0;i<2;i++){
            int row = lr + i*64;
            int kh  = k0 + seg*8;
            int nbK = (K - kh)*2; nbK = nbK < 0 ? 0 : (nbK > 16 ? 16 : nbK);
            int khc = kh < K ? kh : 0;
            const __half* srcA = A + (long)(bm*128+row)*K + khc;
            cp16(&As[buf][row*GST + seg*8], srcA, nbK);
            int brow = bn*128 + row;
            const __half* srcB = B + (long)(brow < N ? brow : 0)*K + khc;
            cp16(&Bs[buf][row*GST + seg*8], srcB, brow < N ? nbK : 0);
        }
    };

    loadStage(0, 0);
    CP_COMMIT();

    for(int kt=0; kt<NT; kt++){
        if(kt+1 < NT){
            loadStage((kt+1)&1, (kt+1)*32);
            CP_COMMIT();
            CP_WAIT1();
        } else {
            CP_WAIT0();
        }
        __syncthreads();

        const int buf = kt&1;
        const uint32_t abase = (uint32_t)__cvta_generic_to_shared(&As[buf][0]);
        const uint32_t bbase = (uint32_t)__cvta_generic_to_shared(&Bs[buf][0]);
        const int lrow = lane & 15, lcol = (lane >> 4) * 8;
        #pragma unroll
        for(int s=0;s<2;s++){
            uint32_t af[2][4];
            #pragma unroll
            for(int mt=0;mt<2;mt++){
                uint32_t ad = abase + ((m0 + mt*16 + lrow)*GST + s*16 + lcol)*2;
                LDSM4(af[mt], ad);
            }
            uint32_t bq[4][4];
            #pragma unroll
            for(int p=0;p<4;p++){
                uint32_t bd = bbase + ((n0 + p*16 + lrow)*GST + s*16 + lcol)*2;
                LDSM4(bq[p], bd);
            }
            #pragma unroll
            for(int mt=0;mt<2;mt++)
                #pragma unroll
                for(int nt=0;nt<8;nt++){
                    uint32_t bf[2] = { bq[nt>>1][nt&1], bq[nt>>1][2+(nt&1)] };
                    mma16(acc[mt][nt], af[mt], bf);
                }
        }
        __syncthreads();
    }

    // ---- epilogue ----
    const int dogelu = flags & 1, out16 = flags & 2;
    float* Cf = (float*)Cv;
    __half* Ch = (__half*)Cv;
    #pragma unroll
    for(int mt=0;mt<2;mt++){
        int r0 = bm*128 + m0 + mt*16 + g;
        int r1 = r0 + 8;
        #pragma unroll
        for(int nt=0;nt<8;nt++){
            int col = bn*128 + n0 + nt*8 + tq*2;
            if(col < N){
                float v0 = acc[mt][nt][0], v1 = acc[mt][nt][1];
                float v2 = acc[mt][nt][2], v3 = acc[mt][nt][3];
                if(bias){ float b0=bias[col], b1=bias[col+1]; v0+=b0; v1+=b1; v2+=b0; v3+=b1; }
                if(dogelu){ v0=gelu_f(v0); v1=gelu_f(v1); v2=gelu_f(v2); v3=gelu_f(v3); }
                long i0 = (long)r0*N + col, i1 = (long)r1*N + col;
                if(out16){
                    *(__half2*)(Ch + i0) = __floats2half2_rn(v0, v1);
                    *(__half2*)(Ch + i1) = __floats2half2_rn(v2, v3);
                } else {
                    if(res){ v0+=res[i0]; v1+=res[i0+1]; v2+=res[i1]; v3+=res[i1+1]; }
                    Cf[i0]=v0; Cf[i0+1]=v1; Cf[i1]=v2; Cf[i1+1]=v3;
                }
            }
        }
    }
}

// ---------------- fused flash attention (fp16 in, fp16 out) ----------------
#define QST 44
#define VST 36

__global__ __launch_bounds__(256)
void flash_attn(const __half* __restrict__ q2, const __half* __restrict__ k2,
                const __half* __restrict__ v2t, __half* __restrict__ attn)
{
    __shared__ uint32_t Qs[128*QST];
    __shared__ uint32_t Ks[64*QST];
    __shared__ uint32_t Vs[72*VST];

    const int tid = threadIdx.x;
    const int lane = tid & 31, w = tid >> 5;
    const int g = lane >> 2, tq = lane & 3;
    const int qb = blockIdx.x, bh = blockIdx.y;

    const __half* Qg = q2 + ((long)bh*IMG_TOK + qb*128)*HD;
    for(int idx = tid; idx < 128*40; idx += 256){
        int r = idx/40, c = idx%40;
        Qs[r*QST + c] = (c < 36) ? *(const uint32_t*)(Qg + (long)r*HD + 2*c) : 0u;
    }
    __syncthreads();

    uint32_t qf[5][4];
    #pragma unroll
    for(int s=0;s<5;s++){
        qf[s][0] = Qs[(w*16+g  )*QST + s*8 + tq    ];
        qf[s][1] = Qs[(w*16+8+g)*QST + s*8 + tq    ];
        qf[s][2] = Qs[(w*16+g  )*QST + s*8 + tq + 4];
        qf[s][3] = Qs[(w*16+8+g)*QST + s*8 + tq + 4];
    }

    float m0 = -3.4e38f, m1 = -3.4e38f, l0 = 0.f, l1 = 0.f;
    float o[9][4];
    #pragma unroll
    for(int nt=0;nt<9;nt++){ o[nt][0]=0.f; o[nt][1]=0.f; o[nt][2]=0.f; o[nt][3]=0.f; }

    const __half* Kg0 = k2  + (long)bh*IMG_TOK*HD;
    const __half* Vg0 = v2t + (long)bh*HD*IMG_TOK;

    for(int kb=0; kb<16; kb++){
        __syncthreads();
        const __half* Kg = Kg0 + (long)kb*64*HD;
        for(int idx = tid; idx < 64*40; idx += 256){
            int r = idx/40, c = idx%40;
            Ks[r*QST + c] = (c < 36) ? *(const uint32_t*)(Kg + (long)r*HD + 2*c) : 0u;
        }
        const __half* Vg = Vg0 + kb*64;
        for(int idx = tid; idx < 72*32; idx += 256){
            int r = idx/32, c = idx%32;
            Vs[r*VST + c] = *(const uint32_t*)(Vg + (long)r*IMG_TOK + 2*c);
        }
        __syncthreads();

        float sacc[8][4];
        #pragma unroll
        for(int nt=0;nt<8;nt++){ sacc[nt][0]=0.f; sacc[nt][1]=0.f; sacc[nt][2]=0.f; sacc[nt][3]=0.f; }
        #pragma unroll
        for(int s=0;s<5;s++){
            #pragma unroll
            for(int nt=0;nt<8;nt++){
                uint32_t bf[2];
                bf[0] = Ks[(nt*8+g)*QST + s*8 + tq    ];
                bf[1] = Ks[(nt*8+g)*QST + s*8 + tq + 4];
                mma16(sacc[nt], qf[s], bf);
            }
        }

        float rm0 = -3.4e38f, rm1 = -3.4e38f;
        #pragma unroll
        for(int nt=0;nt<8;nt++){
            rm0 = fmaxf(rm0, fmaxf(sacc[nt][0], sacc[nt][1]));
            rm1 = fmaxf(rm1, fmaxf(sacc[nt][2], sacc[nt][3]));
        }
        rm0 = fmaxf(rm0, __shfl_xor_sync(0xffffffffu, rm0, 1));
        rm0 = fmaxf(rm0, __shfl_xor_sync(0xffffffffu, rm0, 2));
        rm1 = fmaxf(rm1, __shfl_xor_sync(0xffffffffu, rm1, 1));
        rm1 = fmaxf(rm1, __shfl_xor_sync(0xffffffffu, rm1, 2));

        float m0n = fmaxf(m0, rm0), m1n = fmaxf(m1, rm1);
        float a0 = __expf(m0 - m0n), a1 = __expf(m1 - m1n);
        m0 = m0n; m1 = m1n;

        float rs0 = 0.f, rs1 = 0.f;
        #pragma unroll
        for(int nt=0;nt<8;nt++){
            sacc[nt][0] = __expf(sacc[nt][0] - m0n);
            sacc[nt][1] = __expf(sacc[nt][1] - m0n);
            sacc[nt][2] = __expf(sacc[nt][2] - m1n);
            sacc[nt][3] = __expf(sacc[nt][3] - m1n);
            rs0 += sacc[nt][0] + sacc[nt][1];
            rs1 += sacc[nt][2] + sacc[nt][3];
        }
        rs0 += __shfl_xor_sync(0xffffffffu, rs0, 1);
        rs0 += __shfl_xor_sync(0xffffffffu, rs0, 2);
        rs1 += __shfl_xor_sync(0xffffffffu, rs1, 1);
        rs1 += __shfl_xor_sync(0xffffffffu, rs1, 2);
        l0 = l0*a0 + rs0;
        l1 = l1*a1 + rs1;

        #pragma unroll
        for(int nt=0;nt<9;nt++){
            o[nt][0]*=a0; o[nt][1]*=a0; o[nt][2]*=a1; o[nt][3]*=a1;
        }

        #pragma unroll
        for(int ks=0;ks<4;ks++){
            uint32_t pf[4];
            pf[0] = h2u(sacc[2*ks  ][0], sacc[2*ks  ][1]);
            pf[1] = h2u(sacc[2*ks  ][2], sacc[2*ks  ][3]);
            pf[2] = h2u(sacc[2*ks+1][0], sacc[2*ks+1][1]);
            pf[3] = h2u(sacc[2*ks+1][2], sacc[2*ks+1][3]);
            #pragma unroll
            for(int nt=0;nt<9;nt++){
                uint32_t bf[2];
                bf[0] = Vs[(nt*8+g)*VST + ks*8 + tq    ];
                bf[1] = Vs[(nt*8+g)*VST + ks*8 + tq + 4];
                mma16(o[nt], pf, bf);
            }
        }
    }

    float inv0 = 1.f/l0, inv1 = 1.f/l1;
    int b = bh >> 4, h = bh & 15;
    int t0 = qb*128 + w*16 + g;
    long base0 = (long)(b*IMG_TOK + t0    )*HIDDEN + h*HD;
    long base1 = (long)(b*IMG_TOK + t0 + 8)*HIDDEN + h*HD;
    #pragma unroll
    for(int nt=0;nt<9;nt++){
        int col = nt*8 + tq*2;
        *(__half2*)(attn + base0 + col) = __floats2half2_rn(o[nt][0]*inv0, o[nt][1]*inv0);
        *(__half2*)(attn + base1 + col) = __floats2half2_rn(o[nt][2]*inv1, o[nt][3]*inv1);
    }
}

// ---------------- LayerNorm (fp32 in, fp16 out) ----------------
__global__ void ln_kernel(const float* __restrict__ x, const float* __restrict__ g,
                          const float* __restrict__ b, __half* __restrict__ y, int N)
{
    __shared__ float sh[32];
    long base = (long)blockIdx.x * N;
    float s=0.f, ss=0.f;
    for(int c=threadIdx.x;c<N;c+=blockDim.x){
        float v = x[base+c]; s += v; ss += v*v;
    }
    s  = blockReduceSum(s,  sh);
    ss = blockReduceSum(ss, sh);
    float mu  = s  / (float)N;
    float var = ss / (float)N - mu*mu;
    float rs  = rsqrtf(var + 1e-6f);
    for(int c=threadIdx.x;c<N;c+=blockDim.x){
        y[base+c] = __float2half((x[base+c]-mu)*rs*g[c] + b[c]);
    }
}

// ---------------- RoPE tables ----------------
__global__ void init_rope()
{
    int gid = blockIdx.x*blockDim.x + threadIdx.x;
    if(gid >= IMG_TOK*HD) return;
    int d = gid % HD, tt = gid / HD;
    int iw=tt&1, ih=(tt>>1)&1, bw=(tt>>2)&15, bh=tt>>6;
    int gh = bh*2+ih, gw = bw*2+iw;
    int dd = d % 36;
    int pos, i;
    if(dd < 18){ i = dd;      pos = gh; }
    else       { i = dd - 18; pos = gw; }
    float inv = powf(10000.0f, -((float)(2*i)/36.0f));
    float ang = (float)pos * inv;
    g_cos[gid] = cosf(ang);
    g_sin[gid] = sinf(ang);
}

// ---------------- pos-embed bilinear add ----------------
__global__ void add_pos(float* __restrict__ x, const float* __restrict__ pe)
{
    int gid = blockIdx.x*blockDim.x + threadIdx.x;
    if(gid >= SEQ*HIDDEN) return;
    int j = gid % HIDDEN; int s = gid / HIDDEN;
    int tt = s & 1023;
    int iw=tt&1, ih=(tt>>1)&1, bw=(tt>>2)&15, bh=tt>>6;
    int gh = bh*2+ih, gw = bw*2+iw;
    double hl = (double)gh*47.0/31.0;
    double wl = (double)gw*47.0/31.0;
    int h0=(int)hl; int h1=min(h0+1,47); float dh=(float)(hl-(double)h0);
    int w0=(int)wl; int w1=min(w0+1,47); float dw=(float)(wl-(double)w0);
    float p00 = pe[(h0*48+w0)*HIDDEN + j];
    float p01 = pe[(h0*48+w1)*HIDDEN + j];
    float p10 = pe[(h1*48+w0)*HIDDEN + j];
    float p11 = pe[(h1*48+w1)*HIDDEN + j];
    float v = (1.f-dh)*((1.f-dw)*p00 + dw*p01) + dh*((1.f-dw)*p10 + dw*p11);
    x[gid] += v;
}

// ---------------- RoPE apply + repack (fp16 out, V transposed) ----------------
__global__ void rope_pack(const float* __restrict__ qkv, __half* __restrict__ q2,
                          __half* __restrict__ k2, __half* __restrict__ v2t)
{
    int gid = blockIdx.x*blockDim.x + threadIdx.x;
    if(gid >= SEQ*HEADS*HD) return;
    int d = gid % HD;
    int h = (gid / HD) % HEADS;
    int s = gid / (HD*HEADS);
    int tt = s & (IMG_TOK-1);
    int b = s >> 10;
    float c  = g_cos[tt*HD + d];
    float sn = g_sin[tt*HD + d];
    long base = (long)s*(3*HIDDEN) + h*HD;
    float qd = qkv[base + d];
    float kd = qkv[base + HIDDEN + d];
    int   dp  = (d<36) ? d+36 : d-36;
    float sgn = (d<36) ? -1.f : 1.f;
    float qp = qkv[base + dp];
    float kp = qkv[base + HIDDEN + dp];
    long oi = ((long)(b*HEADS + h)*IMG_TOK + tt)*HD + d;
    q2[oi] = __float2half((qd*c + sgn*qp*sn) * SCALE_Q);
    k2[oi] = __float2half( kd*c + sgn*kp*sn);
    v2t[((long)(b*HEADS + h)*HD + d)*IMG_TOK + tt] = __float2half(qkv[base + 2*HIDDEN + d]);
}

// ---------------- host helpers ----------------
static inline void gemma(const __half*A,const __half*B,void*C,const float*bias,const float*res,
                         int M,int N,int K,int flags){
    dim3 g((N+127)/128, M/128);
    gemm_a<<<g,256>>>(A,B,C,bias,res,M,N,K,flags);
}

extern "C" void kernel_launch(void* const* d_in, const int* in_sizes, int n_in,
                              void* d_out, int out_size)
{
    const float* pixel   = (const float*)d_in[0];
    const float* patch_w = (const float*)d_in[1];
    const float* patch_b = (const float*)d_in[2];
    const float* pos_e   = (const float*)d_in[3];
    const float* qkv_w   = (const float*)d_in[4];
    const float* qkv_b   = (const float*)d_in[5];
    const float* proj_w  = (const float*)d_in[6];
    const float* proj_b  = (const float*)d_in[7];
    const float* ln1_g   = (const float*)d_in[8];
    const float* ln1_b   = (const float*)d_in[9];
    const float* ln2_g   = (const float*)d_in[10];
    const float* ln2_b   = (const float*)d_in[11];
    const float* fc1_w   = (const float*)d_in[12];
    const float* fc1_b   = (const float*)d_in[13];
    const float* fc2_w   = (const float*)d_in[14];
    const float* fc2_b   = (const float*)d_in[15];
    const float* m_ln_g  = (const float*)d_in[16];
    const float* m_ln_b  = (const float*)d_in[17];
    const float* m_fc1_w = (const float*)d_in[18];
    const float* m_fc1_b = (const float*)d_in[19];
    const float* m_fc2_w = (const float*)d_in[20];
    const float* m_fc2_b = (const float*)d_in[21];
    const float* ds_ln_g = (const float*)d_in[22];
    const float* ds_ln_b = (const float*)d_in[23];
    const float* ds_fc1_w= (const float*)d_in[24];
    const float* ds_fc1_b= (const float*)d_in[25];
    const float* ds_fc2_w= (const float*)d_in[26];
    const float* ds_fc2_b= (const float*)d_in[27];
    float* out = (float*)d_out;

    float *px,*pqkv;
    __half *pw16,*pqw16,*ppw16,*pf1w16,*pf2w16,*pm1w16,*pm2w16,*pd1w16,*pd2w16,*ppx16;
    __half *pxn16,*pq16,*pk16,*pv16t,*pat16,*ph16,*pmh16,*pmf16;
    cudaGetSymbolAddress((void**)&px,    g_x);
    cudaGetSymbolAddress((void**)&pqkv,  g_qkv);
    cudaGetSymbolAddress((void**)&pw16,  w16_patch);
    cudaGetSymbolAddress((void**)&pqw16, w16_qkv);
    cudaGetSymbolAddress((void**)&ppw16, w16_proj);
    cudaGetSymbolAddress((void**)&pf1w16,w16_fc1);
    cudaGetSymbolAddress((void**)&pf2w16,w16_fc2);
    cudaGetSymbolAddress((void**)&pm1w16,w16_mfc1);
    cudaGetSymbolAddress((void**)&pm2w16,w16_mfc2);
    cudaGetSymbolAddress((void**)&pd1w16,w16_dfc1);
    cudaGetSymbolAddress((void**)&pd2w16,w16_dfc2);
    cudaGetSymbolAddress((void**)&ppx16, g_px16);
    cudaGetSymbolAddress((void**)&pxn16, g_xn16);
    cudaGetSymbolAddress((void**)&pq16,  g_q16);
    cudaGetSymbolAddress((void**)&pk16,  g_k16);
    cudaGetSymbolAddress((void**)&pv16t, g_v16t);
    cudaGetSymbolAddress((void**)&pat16, g_at16);
    cudaGetSymbolAddress((void**)&ph16,  g_h16);
    cudaGetSymbolAddress((void**)&pmh16, g_mh16);
    cudaGetSymbolAddress((void**)&pmf16, g_mf16);

    const int EW = 256;
    init_rope<<<(IMG_TOK*HD + EW-1)/EW, EW>>>();

    // one-shot fp32 -> fp16 conversions
    auto F2H = [&](const float* s, __half* d, long n){
        int grid = (int)((n + 511)/512); if(grid > 8192) grid = 8192;
        f2h<<<grid, 512>>>(s, d, n);
    };
    F2H(pixel,    ppx16,  (long)SEQ*PATCHD);
    F2H(patch_w,  pw16,   (long)HIDDEN*PATCHD);
    F2H(qkv_w,    pqw16,  (long)DEPTH*3*HIDDEN*HIDDEN);
    F2H(proj_w,   ppw16,  (long)DEPTH*HIDDEN*HIDDEN);
    F2H(fc1_w,    pf1w16, (long)DEPTH*INTER*HIDDEN);
    F2H(fc2_w,    pf2w16, (long)DEPTH*HIDDEN*INTER);
    F2H(m_fc1_w,  pm1w16, (long)MERGED*MERGED);
    F2H(m_fc2_w,  pm2w16, (long)OUTH*MERGED);
    F2H(ds_fc1_w, pd1w16, (long)2*MERGED*MERGED);
    F2H(ds_fc2_w, pd2w16, (long)2*OUTH*MERGED);

    // patch embed + pos embed
    gemma(ppx16, pw16, px, patch_b, nullptr, SEQ, HIDDEN, PATCHD, 0);
    add_pos<<<(SEQ*HIDDEN + EW-1)/EW, EW>>>(px, pos_e);

    const int NQH = SEQ*HEADS*HD;
    for(int i=0;i<DEPTH;i++){
        ln_kernel<<<SEQ,256>>>(px, ln1_g+(long)i*HIDDEN, ln1_b+(long)i*HIDDEN, pxn16, HIDDEN);
        gemma(pxn16, pqw16+(long)i*3*HIDDEN*HIDDEN, pqkv, qkv_b+(long)i*3*HIDDEN, nullptr,
              SEQ, 3*HIDDEN, HIDDEN, 0);
        rope_pack<<<(NQH + EW-1)/EW, EW>>>(pqkv, pq16, pk16, pv16t);
        flash_attn<<<dim3(8, NBH), 256>>>(pq16, pk16, pv16t, pat16);
        gemma(pat16, ppw16+(long)i*HIDDEN*HIDDEN, px, proj_b+(long)i*HIDDEN, px,
              SEQ, HIDDEN, HIDDEN, 0);

        ln_kernel<<<SEQ,256>>>(px, ln2_g+(long)i*HIDDEN, ln2_b+(long)i*HIDDEN, pxn16, HIDDEN);
        gemma(pxn16, pf1w16+(long)i*INTER*HIDDEN, ph16, fc1_b+(long)i*INTER, nullptr,
              SEQ, INTER, HIDDEN, 1|2);
        gemma(ph16, pf2w16+(long)i*HIDDEN*INTER, px, fc2_b+(long)i*HIDDEN, px,
              SEQ, HIDDEN, INTER, 0);

        if(i==2 || i==4){
            int j = (i==2) ? 0 : 1;
            ln_kernel<<<1024,256>>>(px, ds_ln_g+(long)j*MERGED, ds_ln_b+(long)j*MERGED, pmh16, MERGED);
            gemma(pmh16, pd1w16+(long)j*MERGED*MERGED, pmf16, ds_fc1_b+(long)j*MERGED, nullptr,
                  1024, MERGED, MERGED, 1|2);
            gemma(pmf16, pd2w16+(long)j*OUTH*MERGED, out+(long)(1+j)*1024*OUTH,
                  ds_fc2_b+(long)j*OUTH, nullptr,
                  1024, OUTH, MERGED, 0);
        }
    }

    ln_kernel<<<SEQ,256>>>(px, m_ln_g, m_ln_b, pmh16, HIDDEN);
    gemma(pmh16, pm1w16, pmf16, m_fc1_b, nullptr, 1024, MERGED, MERGED, 1|2);
    gemma(pmf16, pm2w16, out, m_fc2_b, nullptr, 1024, OUTH, MERGED, 0);
}